// round 4
// baseline (speedup 1.0000x reference)
#include <cuda_runtime.h>
#include <cstddef>

#define N_NODES 50000
#define N_EDGES 800000
#define D_IN    256
#define D_H     128
#define N_LABELS 1000

// ---------------- scratch (device globals: allocation-free) ----------------
__device__ float g_h[(size_t)N_NODES * D_H];     // 25.6 MB
__device__ float g_agg[(size_t)N_NODES * D_H];   // 25.6 MB
__device__ float g_res[(size_t)N_NODES * D_H];   // 25.6 MB
__device__ int   g_row_ptr[N_NODES + 1];
__device__ int   g_cursor[N_NODES];
__device__ int   g_edge_idx[N_EDGES];
__device__ int   g_block_sums[64];

// ---------------- CSR build (by dst) ----------------
__global__ void k_zero_rowptr() {
    int i = blockIdx.x * blockDim.x + threadIdx.x;
    if (i <= N_NODES) g_row_ptr[i] = 0;
}

__global__ void k_hist(const int* __restrict__ dst) {
    int e = blockIdx.x * blockDim.x + threadIdx.x;
    if (e < N_EDGES) atomicAdd(&g_row_ptr[dst[e] + 1], 1);
}

// inclusive scan over row_ptr[0..N_NODES] in 1024-blocks
__global__ void k_scan1() {
    __shared__ int s[1024];
    int idx = blockIdx.x * 1024 + threadIdx.x;
    int v = (idx <= N_NODES) ? g_row_ptr[idx] : 0;
    s[threadIdx.x] = v;
    __syncthreads();
    #pragma unroll
    for (int off = 1; off < 1024; off <<= 1) {
        int t = (threadIdx.x >= off) ? s[threadIdx.x - off] : 0;
        __syncthreads();
        s[threadIdx.x] += t;
        __syncthreads();
    }
    if (idx <= N_NODES) g_row_ptr[idx] = s[threadIdx.x];
    if (threadIdx.x == 1023) g_block_sums[blockIdx.x] = s[1023];
}

__global__ void k_scan2(int nb) {
    if (blockIdx.x == 0 && threadIdx.x == 0) {
        int run = 0;
        for (int i = 0; i < nb; i++) {
            int t = g_block_sums[i];
            g_block_sums[i] = run;
            run += t;
        }
    }
}

__global__ void k_scan3() {
    int idx = blockIdx.x * 1024 + threadIdx.x;
    if (blockIdx.x > 0 && idx <= N_NODES) g_row_ptr[idx] += g_block_sums[blockIdx.x];
}

__global__ void k_init_cursor() {
    int i = blockIdx.x * blockDim.x + threadIdx.x;
    if (i < N_NODES) g_cursor[i] = g_row_ptr[i];
}

__global__ void k_fill(const int* __restrict__ dst) {
    int e = blockIdx.x * blockDim.x + threadIdx.x;
    if (e < N_EDGES) {
        int p = atomicAdd(&g_cursor[dst[e]], 1);
        g_edge_idx[p] = e;
    }
}

// ---------------- aggregation: one warp per dst node, no atomics -----------
// Computes BOTH res (self_w) and agg (ppi_w) from a single gather of h[src].
__global__ void __launch_bounds__(256)
k_aggregate(const int* __restrict__ src,
            const float* __restrict__ sw,
            const float* __restrict__ pw) {
    int warp = (blockIdx.x * blockDim.x + threadIdx.x) >> 5;
    int lane = threadIdx.x & 31;
    if (warp >= N_NODES) return;
    int beg = g_row_ptr[warp];
    int end = g_row_ptr[warp + 1];
    float rx = 0.f, ry = 0.f, rz = 0.f, rw = 0.f;
    float ax = 0.f, ay = 0.f, az = 0.f, aw = 0.f;
    for (int i = beg; i < end; i++) {
        int e = g_edge_idx[i];
        int s = src[e];
        float s_w = sw[e];
        float p_w = pw[e];
        float4 v = __ldg(((const float4*)(g_h + (size_t)s * D_H)) + lane);
        rx += s_w * v.x; ry += s_w * v.y; rz += s_w * v.z; rw += s_w * v.w;
        ax += p_w * v.x; ay += p_w * v.y; az += p_w * v.z; aw += p_w * v.w;
    }
    float4 R = make_float4(rx, ry, rz, rw);
    float4 A4 = make_float4(ax, ay, az, aw);
    ((float4*)(g_res + (size_t)warp * D_H))[lane] = R;
    ((float4*)(g_agg + (size_t)warp * D_H))[lane] = A4;
}

// ---------------- fused SGEMM: C = [relu](A@W + b) [+ res] -----------------
// 128x128 tile, BK=8, 256 threads, 8x8 per-thread micro-tile.
template<bool RELU, bool RES>
__global__ void __launch_bounds__(256)
k_gemm(const float* __restrict__ A, const float* __restrict__ W,
       const float* __restrict__ bias, const float* __restrict__ res,
       float* __restrict__ C, int M, int K, int Nc) {
    __shared__ float As[8][128];
    __shared__ float Bs[8][132];

    int tid  = threadIdx.x;
    int brow = blockIdx.y * 128;
    int bcol = blockIdx.x * 128;

    int tr = (tid / 16) * 8;   // 0..120
    int tc = (tid % 16) * 8;   // 0..120

    // global-load assignments (one float4 each for A-tile and B-tile)
    int aRow = tid >> 1;            // 0..127
    int aCol = (tid & 1) * 4;       // 0 or 4
    int bRow = tid >> 5;            // 0..7
    int bCol = (tid & 31) * 4;      // 0..124

    float acc[8][8];
    #pragma unroll
    for (int i = 0; i < 8; i++)
        #pragma unroll
        for (int j = 0; j < 8; j++) acc[i][j] = 0.f;

    for (int k0 = 0; k0 < K; k0 += 8) {
        // A tile (128 rows x 8 cols), stored transposed As[k][row]
        float4 av = make_float4(0.f, 0.f, 0.f, 0.f);
        int gr = brow + aRow;
        if (gr < M) av = *(const float4*)(A + (size_t)gr * K + k0 + aCol);
        As[aCol + 0][aRow] = av.x;
        As[aCol + 1][aRow] = av.y;
        As[aCol + 2][aRow] = av.z;
        As[aCol + 3][aRow] = av.w;
        // B tile (8 rows x 128 cols)
        {
            int gc = bcol + bCol;
            const float* wrow = W + (size_t)(k0 + bRow) * Nc;
            float4 bv;
            if (gc + 3 < Nc) {
                bv = *(const float4*)(wrow + gc);
            } else {
                bv.x = (gc + 0 < Nc) ? wrow[gc + 0] : 0.f;
                bv.y = (gc + 1 < Nc) ? wrow[gc + 1] : 0.f;
                bv.z = (gc + 2 < Nc) ? wrow[gc + 2] : 0.f;
                bv.w = (gc + 3 < Nc) ? wrow[gc + 3] : 0.f;
            }
            *(float4*)&Bs[bRow][bCol] = bv;
        }
        __syncthreads();

        #pragma unroll
        for (int k = 0; k < 8; k++) {
            float a[8], b[8];
            *(float4*)(a + 0) = *(const float4*)&As[k][tr + 0];
            *(float4*)(a + 4) = *(const float4*)&As[k][tr + 4];
            *(float4*)(b + 0) = *(const float4*)&Bs[k][tc + 0];
            *(float4*)(b + 4) = *(const float4*)&Bs[k][tc + 4];
            #pragma unroll
            for (int i = 0; i < 8; i++)
                #pragma unroll
                for (int j = 0; j < 8; j++)
                    acc[i][j] += a[i] * b[j];
        }
        __syncthreads();
    }

    // epilogue — hoist bias loads out of the row loop
    float bv[8];
    #pragma unroll
    for (int j = 0; j < 8; j++) {
        int col = bcol + tc + j;
        bv[j] = (col < Nc) ? bias[col] : 0.f;
    }
    #pragma unroll
    for (int i = 0; i < 8; i++) {
        int row = brow + tr + i;
        if (row >= M) continue;
        #pragma unroll
        for (int j = 0; j < 8; j++) {
            int col = bcol + tc + j;
            if (col >= Nc) continue;
            float v = acc[i][j] + bv[j];
            if (RELU) v = fmaxf(v, 0.f);
            if (RES) v += res[(size_t)row * D_H + col];
            C[(size_t)row * Nc + col] = v;
        }
    }
}

// ---------------- launch ----------------
extern "C" void kernel_launch(void* const* d_in, const int* in_sizes, int n_in,
                              void* d_out, int out_size) {
    const float* x      = (const float*)d_in[0];
    const int*   src    = (const int*)d_in[1];
    const int*   dst    = (const int*)d_in[2];
    const float* self_w = (const float*)d_in[3];
    const float* ppi_w  = (const float*)d_in[4];
    const float* W_in   = (const float*)d_in[5];
    const float* b_in   = (const float*)d_in[6];
    const float* W1     = (const float*)d_in[7];
    const float* b1     = (const float*)d_in[8];
    const float* W2     = (const float*)d_in[9];
    const float* b2     = (const float*)d_in[10];
    const float* W_out  = (const float*)d_in[11];
    const float* b_out  = (const float*)d_in[12];
    float* out = (float*)d_out;

    float *h, *agg, *res;
    cudaGetSymbolAddress((void**)&h,   g_h);
    cudaGetSymbolAddress((void**)&agg, g_agg);
    cudaGetSymbolAddress((void**)&res, g_res);

    const int SCAN_BLOCKS = (N_NODES + 1 + 1023) / 1024;  // 49

    // CSR build (independent of h; runs while nothing else is pending)
    k_zero_rowptr<<<(N_NODES + 1 + 255) / 256, 256>>>();
    k_hist<<<(N_EDGES + 255) / 256, 256>>>(dst);
    k_scan1<<<SCAN_BLOCKS, 1024>>>();
    k_scan2<<<1, 32>>>(SCAN_BLOCKS);
    k_scan3<<<SCAN_BLOCKS, 1024>>>();
    k_init_cursor<<<(N_NODES + 255) / 256, 256>>>();
    k_fill<<<(N_EDGES + 255) / 256, 256>>>(dst);

    // input linear + ReLU: h = relu(x @ W_in + b_in)
    dim3 gNarrow((D_H + 127) / 128, (N_NODES + 127) / 128);
    k_gemm<true, false><<<gNarrow, 256>>>(x, W_in, b_in, nullptr, h,
                                          N_NODES, D_IN, D_H);

    // two GCN layers
    int aggBlocks = (N_NODES * 32 + 255) / 256;
    k_aggregate<<<aggBlocks, 256>>>(src, self_w, ppi_w);
    k_gemm<true, true><<<gNarrow, 256>>>(agg, W1, b1, res, h,
                                         N_NODES, D_H, D_H);
    k_aggregate<<<aggBlocks, 256>>>(src, self_w, ppi_w);
    k_gemm<true, true><<<gNarrow, 256>>>(agg, W2, b2, res, h,
                                         N_NODES, D_H, D_H);

    // output linear: out = h @ W_out + b_out
    dim3 gOut((N_LABELS + 127) / 128, (N_NODES + 127) / 128);
    k_gemm<false, false><<<gOut, 256>>>(h, W_out, b_out, nullptr, out,
                                        N_NODES, D_H, N_LABELS);
}

// round 5
// speedup vs baseline: 1.2344x; 1.2344x over previous
#include <cuda_runtime.h>
#include <cstddef>

#define N_NODES 50000
#define N_EDGES 800000
#define D_IN    256
#define D_H     128
#define N_LABELS 1000

// ---------------- scratch (device globals: allocation-free) ----------------
__device__ float g_h[(size_t)N_NODES * D_H];     // 25.6 MB
__device__ float g_agg[(size_t)N_NODES * D_H];   // 25.6 MB
__device__ float g_res[(size_t)N_NODES * D_H];   // 25.6 MB
__device__ int   g_row_ptr[N_NODES + 1];
__device__ int   g_cursor[N_NODES];
__device__ int   g_edge_idx[N_EDGES];

// ---------------- CSR build (by dst) ----------------
__global__ void k_zero_rowptr() {
    int i = blockIdx.x * blockDim.x + threadIdx.x;
    if (i <= N_NODES) g_row_ptr[i] = 0;
}

__global__ void k_hist(const int* __restrict__ dst) {
    int e = blockIdx.x * blockDim.x + threadIdx.x;
    if (e < N_EDGES) atomicAdd(&g_row_ptr[dst[e] + 1], 1);
}

// Fused single-block inclusive scan over g_row_ptr[0..N_NODES] (shuffle-based)
// + writes g_cursor[i] = scanned row_ptr[i]. Replaces scan1/scan2/scan3/init_cursor.
__global__ void __launch_bounds__(1024) k_scan_fused() {
    __shared__ int warp_sums[32];
    __shared__ int carry_s;
    int tid = threadIdx.x, lane = tid & 31, wid = tid >> 5;
    if (tid == 0) carry_s = 0;
    __syncthreads();
    for (int base = 0; base <= N_NODES; base += 1024) {
        int idx = base + tid;
        int v = (idx <= N_NODES) ? g_row_ptr[idx] : 0;
        // warp inclusive scan
        int x = v;
        #pragma unroll
        for (int off = 1; off < 32; off <<= 1) {
            int t = __shfl_up_sync(0xffffffff, x, off);
            if (lane >= off) x += t;
        }
        if (lane == 31) warp_sums[wid] = x;
        __syncthreads();
        if (wid == 0) {
            int w = warp_sums[lane];
            #pragma unroll
            for (int off = 1; off < 32; off <<= 1) {
                int t = __shfl_up_sync(0xffffffff, w, off);
                if (lane >= off) w += t;
            }
            warp_sums[lane] = w;
        }
        __syncthreads();
        int warp_off = (wid > 0) ? warp_sums[wid - 1] : 0;
        int out = x + warp_off + carry_s;
        if (idx <= N_NODES) {
            g_row_ptr[idx] = out;
            if (idx < N_NODES) g_cursor[idx] = out;
        }
        __syncthreads();            // all reads of carry_s / warp_sums done
        if (tid == 1023) carry_s = out;
        __syncthreads();
    }
}

__global__ void k_fill(const int* __restrict__ dst) {
    int e = blockIdx.x * blockDim.x + threadIdx.x;
    if (e < N_EDGES) {
        int p = atomicAdd(&g_cursor[dst[e]], 1);
        g_edge_idx[p] = e;
    }
}

// ---------------- aggregation: one warp per dst node, no atomics -----------
// Computes BOTH res (self_w) and agg (ppi_w) from a single gather of h[src].
__global__ void __launch_bounds__(256)
k_aggregate(const int* __restrict__ src,
            const float* __restrict__ sw,
            const float* __restrict__ pw) {
    int warp = (blockIdx.x * blockDim.x + threadIdx.x) >> 5;
    int lane = threadIdx.x & 31;
    if (warp >= N_NODES) return;
    int beg = g_row_ptr[warp];
    int end = g_row_ptr[warp + 1];
    float rx = 0.f, ry = 0.f, rz = 0.f, rw = 0.f;
    float ax = 0.f, ay = 0.f, az = 0.f, aw = 0.f;
    for (int i = beg; i < end; i++) {
        int e = g_edge_idx[i];
        int s = src[e];
        float s_w = sw[e];
        float p_w = pw[e];
        float4 v = __ldg(((const float4*)(g_h + (size_t)s * D_H)) + lane);
        rx += s_w * v.x; ry += s_w * v.y; rz += s_w * v.z; rw += s_w * v.w;
        ax += p_w * v.x; ay += p_w * v.y; az += p_w * v.z; aw += p_w * v.w;
    }
    float4 R = make_float4(rx, ry, rz, rw);
    float4 A4 = make_float4(ax, ay, az, aw);
    ((float4*)(g_res + (size_t)warp * D_H))[lane] = R;
    ((float4*)(g_agg + (size_t)warp * D_H))[lane] = A4;
}

// ---------------- fused SGEMM: C = [relu](A@W + b) [+ res] -----------------
// 128x128 tile, BK=8, 256 threads, 8x8 per-thread micro-tile.
// Mainloop uses Blackwell packed fp32 FMA (fma.rn.f32x2): accumulators packed
// in pairs along the row (i) axis; a-pairs come free from As LDS.128, b is
// dup-packed {b,b}. 32 FFMA2 per k-step vs 64 FFMA -> 2x fma-pipe throughput.
// Bit-exact vs the scalar fp32 version (same per-lane IEEE fp32 FMA order).
template<bool RELU, bool RES>
__global__ void __launch_bounds__(256)
k_gemm(const float* __restrict__ A, const float* __restrict__ W,
       const float* __restrict__ bias, const float* __restrict__ res,
       float* __restrict__ C, int M, int K, int Nc) {
    __shared__ float As[8][128];
    __shared__ float Bs[8][132];

    int tid  = threadIdx.x;
    int brow = blockIdx.y * 128;
    int bcol = blockIdx.x * 128;

    int tr = (tid / 16) * 8;   // 0..120
    int tc = (tid % 16) * 8;   // 0..120

    // global-load assignments (one float4 each for A-tile and B-tile)
    int aRow = tid >> 1;            // 0..127
    int aCol = (tid & 1) * 4;       // 0 or 4
    int bRow = tid >> 5;            // 0..7
    int bCol = (tid & 31) * 4;      // 0..124

    // packed accumulators: acc2[ip][j] = {acc[2ip][j], acc[2ip+1][j]}
    unsigned long long acc2[4][8];
    #pragma unroll
    for (int ip = 0; ip < 4; ip++)
        #pragma unroll
        for (int j = 0; j < 8; j++) acc2[ip][j] = 0ULL;

    for (int k0 = 0; k0 < K; k0 += 8) {
        // A tile (128 rows x 8 cols), stored transposed As[k][row]
        float4 av = make_float4(0.f, 0.f, 0.f, 0.f);
        int gr = brow + aRow;
        if (gr < M) av = *(const float4*)(A + (size_t)gr * K + k0 + aCol);
        As[aCol + 0][aRow] = av.x;
        As[aCol + 1][aRow] = av.y;
        As[aCol + 2][aRow] = av.z;
        As[aCol + 3][aRow] = av.w;
        // B tile (8 rows x 128 cols)
        {
            int gc = bcol + bCol;
            const float* wrow = W + (size_t)(k0 + bRow) * Nc;
            float4 bv;
            if (gc + 3 < Nc) {
                bv = *(const float4*)(wrow + gc);
            } else {
                bv.x = (gc + 0 < Nc) ? wrow[gc + 0] : 0.f;
                bv.y = (gc + 1 < Nc) ? wrow[gc + 1] : 0.f;
                bv.z = (gc + 2 < Nc) ? wrow[gc + 2] : 0.f;
                bv.w = (gc + 3 < Nc) ? wrow[gc + 3] : 0.f;
            }
            *(float4*)&Bs[bRow][bCol] = bv;
        }
        __syncthreads();

        #pragma unroll
        for (int k = 0; k < 8; k++) {
            // a as 4 row-pairs (64-bit aligned: tr is a multiple of 8)
            unsigned long long ap[4];
            const unsigned long long* As64 =
                (const unsigned long long*)&As[k][tr];
            ap[0] = As64[0]; ap[1] = As64[1];
            ap[2] = As64[2]; ap[3] = As64[3];
            // b scalars, then dup-pack {b,b}
            float b[8];
            *(float4*)(b + 0) = *(const float4*)&Bs[k][tc + 0];
            *(float4*)(b + 4) = *(const float4*)&Bs[k][tc + 4];
            unsigned long long bd[8];
            #pragma unroll
            for (int j = 0; j < 8; j++)
                asm("mov.b64 %0, {%1, %1};" : "=l"(bd[j]) : "f"(b[j]));
            #pragma unroll
            for (int ip = 0; ip < 4; ip++)
                #pragma unroll
                for (int j = 0; j < 8; j++)
                    asm("fma.rn.f32x2 %0, %1, %2, %0;"
                        : "+l"(acc2[ip][j]) : "l"(ap[ip]), "l"(bd[j]));
        }
        __syncthreads();
    }

    // unpack accumulators
    float acc[8][8];
    #pragma unroll
    for (int ip = 0; ip < 4; ip++)
        #pragma unroll
        for (int j = 0; j < 8; j++) {
            float lo, hi;
            asm("mov.b64 {%0, %1}, %2;" : "=f"(lo), "=f"(hi)
                                        : "l"(acc2[ip][j]));
            acc[2 * ip + 0][j] = lo;
            acc[2 * ip + 1][j] = hi;
        }

    // epilogue — hoisted bias, vectorized stores when the 8-col span is in-bounds
    float bv[8];
    #pragma unroll
    for (int j = 0; j < 8; j++) {
        int col = bcol + tc + j;
        bv[j] = (col < Nc) ? bias[col] : 0.f;
    }
    bool fullcols = (bcol + tc + 7) < Nc;
    #pragma unroll
    for (int i = 0; i < 8; i++) {
        int row = brow + tr + i;
        if (row >= M) continue;
        float v[8];
        #pragma unroll
        for (int j = 0; j < 8; j++) {
            v[j] = acc[i][j] + bv[j];
            if (RELU) v[j] = fmaxf(v[j], 0.f);
        }
        if (RES) {
            // RES implies Nc == D_H == 128: always fully in-bounds, aligned
            const float4* rp = (const float4*)(res + (size_t)row * D_H + tc);
            float4 r0 = rp[0], r1 = rp[1];
            v[0] += r0.x; v[1] += r0.y; v[2] += r0.z; v[3] += r0.w;
            v[4] += r1.x; v[5] += r1.y; v[6] += r1.z; v[7] += r1.w;
        }
        if (fullcols) {
            float4* cp = (float4*)(C + (size_t)row * Nc + bcol + tc);
            cp[0] = make_float4(v[0], v[1], v[2], v[3]);
            cp[1] = make_float4(v[4], v[5], v[6], v[7]);
        } else {
            #pragma unroll
            for (int j = 0; j < 8; j++) {
                int col = bcol + tc + j;
                if (col < Nc) C[(size_t)row * Nc + col] = v[j];
            }
        }
    }
}

// ---------------- launch ----------------
extern "C" void kernel_launch(void* const* d_in, const int* in_sizes, int n_in,
                              void* d_out, int out_size) {
    const float* x      = (const float*)d_in[0];
    const int*   src    = (const int*)d_in[1];
    const int*   dst    = (const int*)d_in[2];
    const float* self_w = (const float*)d_in[3];
    const float* ppi_w  = (const float*)d_in[4];
    const float* W_in   = (const float*)d_in[5];
    const float* b_in   = (const float*)d_in[6];
    const float* W1     = (const float*)d_in[7];
    const float* b1     = (const float*)d_in[8];
    const float* W2     = (const float*)d_in[9];
    const float* b2     = (const float*)d_in[10];
    const float* W_out  = (const float*)d_in[11];
    const float* b_out  = (const float*)d_in[12];
    float* out = (float*)d_out;

    float *h, *agg, *res;
    cudaGetSymbolAddress((void**)&h,   g_h);
    cudaGetSymbolAddress((void**)&agg, g_agg);
    cudaGetSymbolAddress((void**)&res, g_res);

    // Launch order chosen so ncu (-s 5 -c 1) profiles launch #6 = k_aggregate.
    // (1) input linear + ReLU: h = relu(x @ W_in + b_in)  — independent of CSR
    dim3 gNarrow((D_H + 127) / 128, (N_NODES + 127) / 128);
    k_gemm<true, false><<<gNarrow, 256>>>(x, W_in, b_in, nullptr, h,
                                          N_NODES, D_IN, D_H);

    // (2..5) CSR build
    k_zero_rowptr<<<(N_NODES + 1 + 255) / 256, 256>>>();
    k_hist<<<(N_EDGES + 255) / 256, 256>>>(dst);
    k_scan_fused<<<1, 1024>>>();
    k_fill<<<(N_EDGES + 255) / 256, 256>>>(dst);

    // (6..9) two GCN layers
    int aggBlocks = (N_NODES * 32 + 255) / 256;
    k_aggregate<<<aggBlocks, 256>>>(src, self_w, ppi_w);
    k_gemm<true, true><<<gNarrow, 256>>>(agg, W1, b1, res, h,
                                         N_NODES, D_H, D_H);
    k_aggregate<<<aggBlocks, 256>>>(src, self_w, ppi_w);
    k_gemm<true, true><<<gNarrow, 256>>>(agg, W2, b2, res, h,
                                         N_NODES, D_H, D_H);

    // (10) output linear: out = h @ W_out + b_out
    dim3 gOut((N_LABELS + 127) / 128, (N_NODES + 127) / 128);
    k_gemm<false, false><<<gOut, 256>>>(h, W_out, b_out, nullptr, out,
                                        N_NODES, D_H, N_LABELS);
}

// round 6
// speedup vs baseline: 1.4746x; 1.1946x over previous
#include <cuda_runtime.h>
#include <cstddef>

#define N_NODES 50000
#define N_EDGES 800000
#define D_IN    256
#define D_H     128
#define N_LABELS 1000

// ---------------- scratch (device globals: allocation-free) ----------------
__device__ float g_h[(size_t)N_NODES * D_H];     // 25.6 MB
__device__ float g_agg[(size_t)N_NODES * D_H];   // 25.6 MB
__device__ float g_res[(size_t)N_NODES * D_H];   // 25.6 MB
__device__ __align__(16) int g_row_ptr[N_NODES + 4];
__device__ __align__(16) int g_cursor[N_NODES + 4];
__device__ float4 g_edata[N_EDGES];              // {src_as_float, self_w, ppi_w, 0}

// ---------------- CSR build (by dst) ----------------
__global__ void k_zero_rowptr() {
    int i = blockIdx.x * blockDim.x + threadIdx.x;
    if (i <= N_NODES) g_row_ptr[i] = 0;
}

__global__ void k_hist(const int* __restrict__ dst) {
    int e = blockIdx.x * blockDim.x + threadIdx.x;
    if (e < N_EDGES) atomicAdd(&g_row_ptr[dst[e] + 1], 1);
}

// Single-block inclusive scan over g_row_ptr[0..N_NODES], int4-vectorized
// (4096 elems/iter -> 13 iters). Also writes g_cursor = scanned offsets.
__global__ void __launch_bounds__(1024) k_scan_fused() {
    __shared__ int warp_sums[32];
    __shared__ int carry_s;
    int tid = threadIdx.x, lane = tid & 31, wid = tid >> 5;
    if (tid == 0) carry_s = 0;
    __syncthreads();
    for (int base = 0; base <= N_NODES; base += 4096) {
        int i0 = base + tid * 4;
        int4 v = make_int4(0, 0, 0, 0);
        if (i0 + 3 <= N_NODES) {
            v = *(const int4*)&g_row_ptr[i0];
        } else if (i0 <= N_NODES) {
            v.x = g_row_ptr[i0];
            if (i0 + 1 <= N_NODES) v.y = g_row_ptr[i0 + 1];
            if (i0 + 2 <= N_NODES) v.z = g_row_ptr[i0 + 2];
        }
        int s1 = v.x, s2 = s1 + v.y, s3 = s2 + v.z, s4 = s3 + v.w;
        int x = s4;
        #pragma unroll
        for (int off = 1; off < 32; off <<= 1) {
            int t = __shfl_up_sync(0xffffffff, x, off);
            if (lane >= off) x += t;
        }
        if (lane == 31) warp_sums[wid] = x;
        __syncthreads();
        if (wid == 0) {
            int w = warp_sums[lane];
            #pragma unroll
            for (int off = 1; off < 32; off <<= 1) {
                int t = __shfl_up_sync(0xffffffff, w, off);
                if (lane >= off) w += t;
            }
            warp_sums[lane] = w;
        }
        __syncthreads();
        int carry = carry_s;
        int p = x - s4 + ((wid > 0) ? warp_sums[wid - 1] : 0) + carry;
        int o1 = p + s1, o2 = p + s2, o3 = p + s3, o4 = p + s4;
        if (i0 + 3 <= N_NODES) {
            *(int4*)&g_row_ptr[i0] = make_int4(o1, o2, o3, o4);
        } else if (i0 <= N_NODES) {
            g_row_ptr[i0] = o1;
            if (i0 + 1 <= N_NODES) g_row_ptr[i0 + 1] = o2;
            if (i0 + 2 <= N_NODES) g_row_ptr[i0 + 2] = o3;
        }
        if (i0 + 3 < N_NODES) {
            *(int4*)&g_cursor[i0] = make_int4(o1, o2, o3, o4);
        } else if (i0 < N_NODES) {
            g_cursor[i0] = o1;
            if (i0 + 1 < N_NODES) g_cursor[i0 + 1] = o2;
            if (i0 + 2 < N_NODES) g_cursor[i0 + 2] = o3;
            if (i0 + 3 < N_NODES) g_cursor[i0 + 3] = o4;
        }
        __syncthreads();
        if (tid == 0) carry_s = carry + warp_sums[31];
        __syncthreads();
    }
}

// Scatter edges into CSR order, packing {src, self_w, ppi_w} per edge so the
// aggregation loop has one uniform LDG.128 + one gather per edge.
__global__ void k_fill(const int* __restrict__ src, const int* __restrict__ dst,
                       const float* __restrict__ sw, const float* __restrict__ pw) {
    int e = blockIdx.x * blockDim.x + threadIdx.x;
    if (e < N_EDGES) {
        int p = atomicAdd(&g_cursor[dst[e]], 1);
        float4 t;
        t.x = __int_as_float(src[e]);
        t.y = sw[e];
        t.z = pw[e];
        t.w = 0.f;
        g_edata[p] = t;
    }
}

// ---------------- aggregation: one warp per dst node, no atomics -----------
// Computes BOTH res (self_w) and agg (ppi_w) from a single gather of h[src].
__global__ void __launch_bounds__(256)
k_aggregate() {
    int warp = (blockIdx.x * blockDim.x + threadIdx.x) >> 5;
    int lane = threadIdx.x & 31;
    if (warp >= N_NODES) return;
    int beg = g_row_ptr[warp];
    int end = g_row_ptr[warp + 1];
    float rx = 0.f, ry = 0.f, rz = 0.f, rw = 0.f;
    float ax = 0.f, ay = 0.f, az = 0.f, aw = 0.f;
    for (int i = beg; i < end; i++) {
        float4 t = __ldg(&g_edata[i]);
        int s = __float_as_int(t.x);
        float s_w = t.y;
        float p_w = t.z;
        float4 v = __ldg(((const float4*)(g_h + (size_t)s * D_H)) + lane);
        rx += s_w * v.x; ry += s_w * v.y; rz += s_w * v.z; rw += s_w * v.w;
        ax += p_w * v.x; ay += p_w * v.y; az += p_w * v.z; aw += p_w * v.w;
    }
    ((float4*)(g_res + (size_t)warp * D_H))[lane] = make_float4(rx, ry, rz, rw);
    ((float4*)(g_agg + (size_t)warp * D_H))[lane] = make_float4(ax, ay, az, aw);
}

// ---------------- fused SGEMM: C = [relu](A@W + b) [+ res] -----------------
// 128x128 tile, BK=8, 256 threads, 16x4 per-thread micro-tile, FFMA2
// (fma.rn.f32x2) with row-pair-packed accumulators, double-buffered SMEM
// (one __syncthreads per tile, LDG prefetch hidden under compute).
// a-reads: warp-uniform broadcast LDS; b-reads: conflict-free 16B-stride LDS.
template<bool RELU, bool RES>
__global__ void __launch_bounds__(256, 2)
k_gemm(const float* __restrict__ A, const float* __restrict__ W,
       const float* __restrict__ bias, const float* __restrict__ res,
       float* __restrict__ C, int M, int K, int Nc) {
    __shared__ float As[2][8][128];
    __shared__ float Bs[2][8][132];

    int tid  = threadIdx.x;
    int brow = blockIdx.y * 128;
    int bcol = blockIdx.x * 128;

    int tr = (tid >> 5) * 16;   // 0..112 (warp-uniform)
    int tc = (tid & 31) * 4;    // 0..124

    int aRow = tid >> 1;        // 0..127
    int aCol = (tid & 1) * 4;   // 0 or 4
    int bRow = tid >> 5;        // 0..7
    int bCol = (tid & 31) * 4;  // 0..124

    int gr = brow + aRow;
    const float* Abase = A + (size_t)gr * K + aCol;
    int gc = bcol + bCol;

    // packed accumulators: acc2[ip][j] = {acc[2ip][j], acc[2ip+1][j]}
    unsigned long long acc2[8][4];
    #pragma unroll
    for (int ip = 0; ip < 8; ip++)
        #pragma unroll
        for (int j = 0; j < 4; j++) acc2[ip][j] = 0ULL;

    int nT = K / 8;

    // load tile 0 into buffer 0
    {
        float4 av = make_float4(0.f, 0.f, 0.f, 0.f);
        if (gr < M) av = *(const float4*)(Abase + 0);
        As[0][aCol + 0][aRow] = av.x;
        As[0][aCol + 1][aRow] = av.y;
        As[0][aCol + 2][aRow] = av.z;
        As[0][aCol + 3][aRow] = av.w;
        const float* wrow = W + (size_t)bRow * Nc;
        float4 bv;
        if (gc + 3 < Nc) {
            bv = *(const float4*)(wrow + gc);
        } else {
            bv.x = (gc + 0 < Nc) ? wrow[gc + 0] : 0.f;
            bv.y = (gc + 1 < Nc) ? wrow[gc + 1] : 0.f;
            bv.z = (gc + 2 < Nc) ? wrow[gc + 2] : 0.f;
            bv.w = (gc + 3 < Nc) ? wrow[gc + 3] : 0.f;
        }
        *(float4*)&Bs[0][bRow][bCol] = bv;
    }
    __syncthreads();

    for (int t = 0; t < nT; t++) {
        int cur = t & 1;
        // prefetch next tile's globals into registers (latency hidden by compute)
        float4 avn, bvn;
        bool has = (t + 1 < nT);
        if (has) {
            int k0 = (t + 1) * 8;
            avn = make_float4(0.f, 0.f, 0.f, 0.f);
            if (gr < M) avn = *(const float4*)(Abase + k0);
            const float* wrow = W + (size_t)(k0 + bRow) * Nc;
            if (gc + 3 < Nc) {
                bvn = *(const float4*)(wrow + gc);
            } else {
                bvn.x = (gc + 0 < Nc) ? wrow[gc + 0] : 0.f;
                bvn.y = (gc + 1 < Nc) ? wrow[gc + 1] : 0.f;
                bvn.z = (gc + 2 < Nc) ? wrow[gc + 2] : 0.f;
                bvn.w = (gc + 3 < Nc) ? wrow[gc + 3] : 0.f;
            }
        }

        // compute on current buffer
        #pragma unroll
        for (int k = 0; k < 8; k++) {
            unsigned long long ap[8];
            const unsigned long long* As64 =
                (const unsigned long long*)&As[cur][k][tr];
            #pragma unroll
            for (int q = 0; q < 8; q++) ap[q] = As64[q];
            float b[4];
            *(float4*)b = *(const float4*)&Bs[cur][k][tc];
            unsigned long long bd[4];
            #pragma unroll
            for (int j = 0; j < 4; j++)
                asm("mov.b64 %0, {%1, %1};" : "=l"(bd[j]) : "f"(b[j]));
            #pragma unroll
            for (int ip = 0; ip < 8; ip++)
                #pragma unroll
                for (int j = 0; j < 4; j++)
                    asm("fma.rn.f32x2 %0, %1, %2, %0;"
                        : "+l"(acc2[ip][j]) : "l"(ap[ip]), "l"(bd[j]));
        }

        // stage next tile into the other buffer
        if (has) {
            int nxt = cur ^ 1;
            As[nxt][aCol + 0][aRow] = avn.x;
            As[nxt][aCol + 1][aRow] = avn.y;
            As[nxt][aCol + 2][aRow] = avn.z;
            As[nxt][aCol + 3][aRow] = avn.w;
            *(float4*)&Bs[nxt][bRow][bCol] = bvn;
        }
        __syncthreads();
    }

    // unpack accumulators: rows 2ip, 2ip+1
    float acc[16][4];
    #pragma unroll
    for (int ip = 0; ip < 8; ip++)
        #pragma unroll
        for (int j = 0; j < 4; j++) {
            float lo, hi;
            asm("mov.b64 {%0, %1}, %2;" : "=f"(lo), "=f"(hi)
                                        : "l"(acc2[ip][j]));
            acc[2 * ip + 0][j] = lo;
            acc[2 * ip + 1][j] = hi;
        }

    // epilogue
    float bv4[4];
    #pragma unroll
    for (int j = 0; j < 4; j++) {
        int col = bcol + tc + j;
        bv4[j] = (col < Nc) ? bias[col] : 0.f;
    }
    bool fullcols = (bcol + tc + 3) < Nc;
    #pragma unroll
    for (int i = 0; i < 16; i++) {
        int row = brow + tr + i;
        if (row >= M) continue;
        float v[4];
        #pragma unroll
        for (int j = 0; j < 4; j++) {
            v[j] = acc[i][j] + bv4[j];
            if (RELU) v[j] = fmaxf(v[j], 0.f);
        }
        if (RES) {
            // RES implies Nc == D_H == 128: fully in-bounds, 16B-aligned
            float4 r = *(const float4*)(res + (size_t)row * D_H + tc);
            v[0] += r.x; v[1] += r.y; v[2] += r.z; v[3] += r.w;
        }
        if (fullcols) {
            *(float4*)(C + (size_t)row * Nc + bcol + tc) =
                make_float4(v[0], v[1], v[2], v[3]);
        } else {
            #pragma unroll
            for (int j = 0; j < 4; j++) {
                int col = bcol + tc + j;
                if (col < Nc) C[(size_t)row * Nc + col] = v[j];
            }
        }
    }
}

// ---------------- launch ----------------
extern "C" void kernel_launch(void* const* d_in, const int* in_sizes, int n_in,
                              void* d_out, int out_size) {
    const float* x      = (const float*)d_in[0];
    const int*   src    = (const int*)d_in[1];
    const int*   dst    = (const int*)d_in[2];
    const float* self_w = (const float*)d_in[3];
    const float* ppi_w  = (const float*)d_in[4];
    const float* W_in   = (const float*)d_in[5];
    const float* b_in   = (const float*)d_in[6];
    const float* W1     = (const float*)d_in[7];
    const float* b1     = (const float*)d_in[8];
    const float* W2     = (const float*)d_in[9];
    const float* b2     = (const float*)d_in[10];
    const float* W_out  = (const float*)d_in[11];
    const float* b_out  = (const float*)d_in[12];
    float* out = (float*)d_out;

    float *h, *agg, *res;
    cudaGetSymbolAddress((void**)&h,   g_h);
    cudaGetSymbolAddress((void**)&agg, g_agg);
    cudaGetSymbolAddress((void**)&res, g_res);

    dim3 gNarrow((D_H + 127) / 128, (N_NODES + 127) / 128);
    dim3 gOut((N_LABELS + 127) / 128, (N_NODES + 127) / 128);
    int aggBlocks = (N_NODES * 32 + 255) / 256;

    // ncu (empirically) profiles launch #4 -> put the input GEMM there.
    k_zero_rowptr<<<(N_NODES + 1 + 255) / 256, 256>>>();          // 1
    k_hist<<<(N_EDGES + 255) / 256, 256>>>(dst);                  // 2
    k_scan_fused<<<1, 1024>>>();                                  // 3
    k_gemm<true, false><<<gNarrow, 256>>>(x, W_in, b_in, nullptr, // 4 (profiled)
                                          h, N_NODES, D_IN, D_H);
    k_fill<<<(N_EDGES + 255) / 256, 256>>>(src, dst, self_w, ppi_w); // 5

    k_aggregate<<<aggBlocks, 256>>>();                            // 6
    k_gemm<true, true><<<gNarrow, 256>>>(agg, W1, b1, res, h,     // 7
                                         N_NODES, D_H, D_H);
    k_aggregate<<<aggBlocks, 256>>>();                            // 8
    k_gemm<true, true><<<gNarrow, 256>>>(agg, W2, b2, res, h,     // 9
                                         N_NODES, D_H, D_H);

    k_gemm<false, false><<<gOut, 256>>>(h, W_out, b_out, nullptr, // 10
                                        out, N_NODES, D_H, N_LABELS);
}

// round 8
// speedup vs baseline: 2.3916x; 1.6218x over previous
#include <cuda_runtime.h>
#include <cuda_bf16.h>
#include <cstdint>
#include <cstddef>

#define N_NODES 50000
#define N_EDGES 800000
#define D_IN    256
#define D_H     128
#define N_LABELS 1000

// ---------------- scratch (device globals: allocation-free) ----------------
__device__ float g_h[(size_t)N_NODES * D_H];
__device__ float g_res[(size_t)N_NODES * D_H];
__device__ __align__(16) int g_row_ptr[N_NODES + 4];
__device__ __align__(16) int g_cursor[N_NODES + 4];
__device__ float4 g_edata[N_EDGES];              // {src_as_float, self_w, ppi_w, 0}

// split-bf16 operands
__device__ __align__(16) __nv_bfloat16 g_x_hi[(size_t)N_NODES * D_IN];
__device__ __align__(16) __nv_bfloat16 g_x_lo[(size_t)N_NODES * D_IN];
__device__ __align__(16) __nv_bfloat16 g_agg_hi[(size_t)N_NODES * D_H];
__device__ __align__(16) __nv_bfloat16 g_agg_lo[(size_t)N_NODES * D_H];
__device__ __align__(16) __nv_bfloat16 g_h_hi[(size_t)N_NODES * D_H];
__device__ __align__(16) __nv_bfloat16 g_h_lo[(size_t)N_NODES * D_H];
// transposed weight splits: Wt[n][k]
__device__ __align__(16) __nv_bfloat16 g_win_hi[D_H * D_IN];
__device__ __align__(16) __nv_bfloat16 g_win_lo[D_H * D_IN];
__device__ __align__(16) __nv_bfloat16 g_w1_hi[D_H * D_H];
__device__ __align__(16) __nv_bfloat16 g_w1_lo[D_H * D_H];
__device__ __align__(16) __nv_bfloat16 g_w2_hi[D_H * D_H];
__device__ __align__(16) __nv_bfloat16 g_w2_lo[D_H * D_H];
__device__ __align__(16) __nv_bfloat16 g_wout_hi[(size_t)N_LABELS * D_H];
__device__ __align__(16) __nv_bfloat16 g_wout_lo[(size_t)N_LABELS * D_H];

// ---------------- helpers ----------------
__device__ __forceinline__ uint32_t smem_u32(const void* p) {
    uint32_t a;
    asm("{ .reg .u64 t; cvta.to.shared.u64 t, %1; cvt.u32.u64 %0, t; }"
        : "=r"(a) : "l"(p));
    return a;
}
__device__ __forceinline__ uint32_t bpack(__nv_bfloat16 a, __nv_bfloat16 b) {
    return (uint32_t)__bfloat16_as_ushort(a) |
           ((uint32_t)__bfloat16_as_ushort(b) << 16);
}
__device__ __forceinline__ void split1(float v, __nv_bfloat16& h, __nv_bfloat16& l) {
    h = __float2bfloat16_rn(v);
    l = __float2bfloat16_rn(v - __bfloat162float(h));
}
__device__ __forceinline__ void ldsm4(uint32_t* r, uint32_t addr) {
    asm volatile("ldmatrix.sync.aligned.m8n8.x4.shared.b16 {%0,%1,%2,%3}, [%4];"
        : "=r"(r[0]), "=r"(r[1]), "=r"(r[2]), "=r"(r[3]) : "r"(addr));
}
__device__ __forceinline__ void mma16816(float* d, const uint32_t* a, const uint32_t* b) {
    asm volatile("mma.sync.aligned.m16n8k16.row.col.f32.bf16.bf16.f32 "
        "{%0,%1,%2,%3}, {%4,%5,%6,%7}, {%8,%9}, {%0,%1,%2,%3};"
        : "+f"(d[0]), "+f"(d[1]), "+f"(d[2]), "+f"(d[3])
        : "r"(a[0]), "r"(a[1]), "r"(a[2]), "r"(a[3]), "r"(b[0]), "r"(b[1]));
}
__device__ __forceinline__ void cpasync16(uint32_t dst, const void* src, bool valid) {
    int sz = valid ? 16 : 0;
    asm volatile("cp.async.ca.shared.global [%0], [%1], 16, %2;"
        :: "r"(dst), "l"(src), "r"(sz) : "memory");
}
__device__ __forceinline__ void cp_commit() {
    asm volatile("cp.async.commit_group;" ::: "memory");
}
__device__ __forceinline__ void cp_wait0() {
    asm volatile("cp.async.wait_group 0;" ::: "memory");
}
__device__ __forceinline__ void cp_wait1() {
    asm volatile("cp.async.wait_group 1;" ::: "memory");
}

// ---------------- prep: zero rowptr + split x + split/transpose Ws ---------
__global__ void k_prep(const float* __restrict__ x, const float* __restrict__ Win,
                       const float* __restrict__ W1, const float* __restrict__ W2,
                       const float* __restrict__ Wout) {
    const long n0 = N_NODES + 1;
    const long n1 = n0 + (long)N_NODES * D_IN / 4;
    const long n2 = n1 + (long)D_IN * D_H;
    const long n3 = n2 + (long)D_H * D_H;
    const long n4 = n3 + (long)D_H * D_H;
    const long n5 = n4 + (long)D_H * N_LABELS;
    long idx = (long)blockIdx.x * blockDim.x + threadIdx.x;
    if (idx < n0) { g_row_ptr[idx] = 0; return; }
    if (idx < n1) {
        long i = (idx - n0) * 4;
        float4 v = *(const float4*)(x + i);
        __nv_bfloat16 h0, h1, h2, h3, l0, l1, l2, l3;
        split1(v.x, h0, l0); split1(v.y, h1, l1);
        split1(v.z, h2, l2); split1(v.w, h3, l3);
        *(uint2*)(g_x_hi + i) = make_uint2(bpack(h0, h1), bpack(h2, h3));
        *(uint2*)(g_x_lo + i) = make_uint2(bpack(l0, l1), bpack(l2, l3));
        return;
    }
    if (idx < n2) {
        long i = idx - n1; int n = (int)(i % D_H), k = (int)(i / D_H);
        __nv_bfloat16 h, l; split1(Win[(size_t)k * D_H + n], h, l);
        g_win_hi[(size_t)n * D_IN + k] = h; g_win_lo[(size_t)n * D_IN + k] = l;
        return;
    }
    if (idx < n3) {
        long i = idx - n2; int n = (int)(i % D_H), k = (int)(i / D_H);
        __nv_bfloat16 h, l; split1(W1[(size_t)k * D_H + n], h, l);
        g_w1_hi[(size_t)n * D_H + k] = h; g_w1_lo[(size_t)n * D_H + k] = l;
        return;
    }
    if (idx < n4) {
        long i = idx - n3; int n = (int)(i % D_H), k = (int)(i / D_H);
        __nv_bfloat16 h, l; split1(W2[(size_t)k * D_H + n], h, l);
        g_w2_hi[(size_t)n * D_H + k] = h; g_w2_lo[(size_t)n * D_H + k] = l;
        return;
    }
    if (idx < n5) {
        long i = idx - n4; int n = (int)(i % N_LABELS), k = (int)(i / N_LABELS);
        __nv_bfloat16 h, l; split1(Wout[(size_t)k * N_LABELS + n], h, l);
        g_wout_hi[(size_t)n * D_H + k] = h; g_wout_lo[(size_t)n * D_H + k] = l;
        return;
    }
}

// ---------------- CSR build ----------------
__global__ void k_hist(const int* __restrict__ dst) {
    int e = blockIdx.x * blockDim.x + threadIdx.x;
    if (e < N_EDGES) atomicAdd(&g_row_ptr[dst[e] + 1], 1);
}

__global__ void __launch_bounds__(1024) k_scan_fused() {
    __shared__ int warp_sums[32];
    __shared__ int carry_s;
    int tid = threadIdx.x, lane = tid & 31, wid = tid >> 5;
    if (tid == 0) carry_s = 0;
    __syncthreads();
    for (int base = 0; base <= N_NODES; base += 4096) {
        int i0 = base + tid * 4;
        int4 v = make_int4(0, 0, 0, 0);
        if (i0 + 3 <= N_NODES) {
            v = *(const int4*)&g_row_ptr[i0];
        } else if (i0 <= N_NODES) {
            v.x = g_row_ptr[i0];
            if (i0 + 1 <= N_NODES) v.y = g_row_ptr[i0 + 1];
            if (i0 + 2 <= N_NODES) v.z = g_row_ptr[i0 + 2];
        }
        int s1 = v.x, s2 = s1 + v.y, s3 = s2 + v.z, s4 = s3 + v.w;
        int x = s4;
        #pragma unroll
        for (int off = 1; off < 32; off <<= 1) {
            int t = __shfl_up_sync(0xffffffff, x, off);
            if (lane >= off) x += t;
        }
        if (lane == 31) warp_sums[wid] = x;
        __syncthreads();
        if (wid == 0) {
            int w = warp_sums[lane];
            #pragma unroll
            for (int off = 1; off < 32; off <<= 1) {
                int t = __shfl_up_sync(0xffffffff, w, off);
                if (lane >= off) w += t;
            }
            warp_sums[lane] = w;
        }
        __syncthreads();
        int carry = carry_s;
        int p = x - s4 + ((wid > 0) ? warp_sums[wid - 1] : 0) + carry;
        int o1 = p + s1, o2 = p + s2, o3 = p + s3, o4 = p + s4;
        if (i0 + 3 <= N_NODES) {
            *(int4*)&g_row_ptr[i0] = make_int4(o1, o2, o3, o4);
        } else if (i0 <= N_NODES) {
            g_row_ptr[i0] = o1;
            if (i0 + 1 <= N_NODES) g_row_ptr[i0 + 1] = o2;
            if (i0 + 2 <= N_NODES) g_row_ptr[i0 + 2] = o3;
        }
        if (i0 + 3 < N_NODES) {
            *(int4*)&g_cursor[i0] = make_int4(o1, o2, o3, o4);
        } else if (i0 < N_NODES) {
            g_cursor[i0] = o1;
            if (i0 + 1 < N_NODES) g_cursor[i0 + 1] = o2;
            if (i0 + 2 < N_NODES) g_cursor[i0 + 2] = o3;
            if (i0 + 3 < N_NODES) g_cursor[i0 + 3] = o4;
        }
        __syncthreads();
        if (tid == 0) carry_s = carry + warp_sums[31];
        __syncthreads();
    }
}

__global__ void k_fill(const int* __restrict__ src, const int* __restrict__ dst,
                       const float* __restrict__ sw, const float* __restrict__ pw) {
    int e = blockIdx.x * blockDim.x + threadIdx.x;
    if (e < N_EDGES) {
        int p = atomicAdd(&g_cursor[dst[e]], 1);
        float4 t;
        t.x = __int_as_float(src[e]);
        t.y = sw[e];
        t.z = pw[e];
        t.w = 0.f;
        g_edata[p] = t;
    }
}

// ---------------- aggregation: warp per node; res fp32 + agg split-bf16 ----
__global__ void __launch_bounds__(256)
k_aggregate() {
    int warp = (blockIdx.x * blockDim.x + threadIdx.x) >> 5;
    int lane = threadIdx.x & 31;
    if (warp >= N_NODES) return;
    int beg = g_row_ptr[warp];
    int end = g_row_ptr[warp + 1];
    float rx = 0.f, ry = 0.f, rz = 0.f, rw = 0.f;
    float ax = 0.f, ay = 0.f, az = 0.f, aw = 0.f;
    for (int i = beg; i < end; i++) {
        float4 t = __ldg(&g_edata[i]);
        int s = __float_as_int(t.x);
        float s_w = t.y;
        float p_w = t.z;
        float4 v = __ldg(((const float4*)(g_h + (size_t)s * D_H)) + lane);
        rx += s_w * v.x; ry += s_w * v.y; rz += s_w * v.z; rw += s_w * v.w;
        ax += p_w * v.x; ay += p_w * v.y; az += p_w * v.z; aw += p_w * v.w;
    }
    ((float4*)(g_res + (size_t)warp * D_H))[lane] = make_float4(rx, ry, rz, rw);
    __nv_bfloat16 h0, h1, h2, h3, l0, l1, l2, l3;
    split1(ax, h0, l0); split1(ay, h1, l1);
    split1(az, h2, l2); split1(aw, h3, l3);
    size_t o = (size_t)warp * D_H + lane * 4;
    *(uint2*)(g_agg_hi + o) = make_uint2(bpack(h0, h1), bpack(h2, h3));
    *(uint2*)(g_agg_lo + o) = make_uint2(bpack(l0, l1), bpack(l2, l3));
}

// ============================================================================
// split-bf16 GEMM on mma.sync.m16n8k16:  C = [relu](A@W + b) [+ res]
//   A split: Ahi/Alo [M,K] bf16 row-major. B split: Bhi/Blo = W^T [Nc,K].
//   D = Ahi·Bhi + Ahi·Blo + Alo·Bhi  (fp32 acc; dropped lo·lo <= 2^-18 rel).
//   CTA 128x128, 8 warps (4m x 2n), warp tile 32x64, K-chunk 32,
//   cp.async double buffer, 80B-pitch SMEM rows (conflict-free ldmatrix).
// ============================================================================
static constexpr int PITCH = 80;                 // 32 bf16 = 64B + 16B pad
static constexpr int BUF_A = 128 * PITCH;        // 10240 per matrix
static constexpr int OFF_AHI = 0;
static constexpr int OFF_ALO = BUF_A;
static constexpr int OFF_BHI = 2 * BUF_A;
static constexpr int OFF_BLO = 3 * BUF_A;
static constexpr int BUF_STRIDE = 4 * BUF_A;     // 40960
static constexpr int SMEM_GEMM = 2 * BUF_STRIDE; // 81920

template<bool RELU, bool RES, bool SPLITOUT>
__global__ void __launch_bounds__(256, 2)
k_gemm_mma(const __nv_bfloat16* __restrict__ Ahi, const __nv_bfloat16* __restrict__ Alo,
           const __nv_bfloat16* __restrict__ Bhi, const __nv_bfloat16* __restrict__ Blo,
           const float* __restrict__ bias, const float* __restrict__ res,
           float* __restrict__ C, __nv_bfloat16* __restrict__ Chi,
           __nv_bfloat16* __restrict__ Clo, int M, int K, int Nc) {
    extern __shared__ char smem[];
    uint32_t sb = smem_u32(smem);
    int tid = threadIdx.x, l = tid & 31, wid = tid >> 5;
    int brow = blockIdx.y * 128, bcol = blockIdx.x * 128;
    int mbase = (wid & 3) * 32;     // warp m offset
    int nbase = (wid >> 2) * 64;    // warp n offset

    float acc[2][8][4];
    #pragma unroll
    for (int a = 0; a < 2; a++)
        #pragma unroll
        for (int b = 0; b < 8; b++)
            #pragma unroll
            for (int c = 0; c < 4; c++) acc[a][b][c] = 0.f;

    int nCh = K >> 5;

    auto issue_copy = [&](int ch, int buf) {
        int k0 = ch * 32;
        uint32_t base = sb + buf * BUF_STRIDE;
        #pragma unroll
        for (int it = 0; it < 2; it++) {
            int idx = tid + it * 256;
            int row = idx >> 2, seg = idx & 3;
            uint32_t soff = row * PITCH + seg * 16;
            int gr = brow + row;
            bool va = gr < M;
            size_t aoff = (size_t)gr * K + k0 + seg * 8;
            cpasync16(base + OFF_AHI + soff, Ahi + aoff, va);
            cpasync16(base + OFF_ALO + soff, Alo + aoff, va);
            int gn = bcol + row;
            bool vb = gn < Nc;
            size_t boff = (size_t)gn * K + k0 + seg * 8;
            cpasync16(base + OFF_BHI + soff, Bhi + boff, vb);
            cpasync16(base + OFF_BLO + soff, Blo + boff, vb);
        }
        cp_commit();
    };

    issue_copy(0, 0);
    for (int ch = 0; ch < nCh; ch++) {
        int buf = ch & 1;
        if (ch + 1 < nCh) { issue_copy(ch + 1, buf ^ 1); cp_wait1(); }
        else cp_wait0();
        __syncthreads();

        uint32_t bA_hi = sb + buf * BUF_STRIDE + OFF_AHI;
        uint32_t bA_lo = sb + buf * BUF_STRIDE + OFF_ALO;
        uint32_t bB_hi = sb + buf * BUF_STRIDE + OFF_BHI;
        uint32_t bB_lo = sb + buf * BUF_STRIDE + OFF_BLO;

        #pragma unroll
        for (int ks = 0; ks < 2; ks++) {
            // A fragments: addr lanes 0-15 -> rows, col 0; 16-31 -> rows, col 8
            uint32_t aH[2][4], aL[2][4];
            #pragma unroll
            for (int mt = 0; mt < 2; mt++) {
                uint32_t ad = (uint32_t)((mbase + mt * 16 + (l & 15)) * PITCH
                                          + ks * 32 + (l >> 4) * 16);
                ldsm4(aH[mt], bA_hi + ad);
                ldsm4(aL[mt], bA_lo + ad);
            }
            #pragma unroll
            for (int np = 0; np < 4; np++) {
                // B x4: lanes 0-7 nt0/k0, 8-15 nt0/k8, 16-23 nt1/k0, 24-31 nt1/k8
                uint32_t nrow = (uint32_t)(nbase + np * 16 + (l & 7) + ((l >> 4) << 3));
                uint32_t bd = nrow * PITCH + ks * 32 + (((l >> 3) & 1) << 4);
                uint32_t bH[4], bL[4];
                ldsm4(bH, bB_hi + bd);
                ldsm4(bL, bB_lo + bd);
                #pragma unroll
                for (int mt = 0; mt < 2; mt++) {
                    mma16816(acc[mt][np * 2 + 0], aH[mt], bH + 0);
                    mma16816(acc[mt][np * 2 + 0], aH[mt], bL + 0);
                    mma16816(acc[mt][np * 2 + 0], aL[mt], bH + 0);
                    mma16816(acc[mt][np * 2 + 1], aH[mt], bH + 2);
                    mma16816(acc[mt][np * 2 + 1], aH[mt], bL + 2);
                    mma16816(acc[mt][np * 2 + 1], aL[mt], bH + 2);
                }
            }
        }
        __syncthreads();
    }

    // epilogue: lane l holds (row = l/4 [+8], cols = 2*(l%4)+{0,1}) per tile
    int rl = l >> 2;
    int cq = (l & 3) * 2;
    float b0v[8], b1v[8];
    bool cok[8];
    #pragma unroll
    for (int nt = 0; nt < 8; nt++) {
        int c = bcol + nbase + nt * 8 + cq;
        cok[nt] = c < Nc;
        b0v[nt] = cok[nt] ? bias[c] : 0.f;
        b1v[nt] = cok[nt] ? bias[c + 1] : 0.f;
    }
    #pragma unroll
    for (int mt = 0; mt < 2; mt++) {
        #pragma unroll
        for (int half = 0; half < 2; half++) {
            int r = brow + mbase + mt * 16 + rl + half * 8;
            if (r >= M) continue;
            #pragma unroll
            for (int nt = 0; nt < 8; nt++) {
                if (!cok[nt]) continue;
                int c = bcol + nbase + nt * 8 + cq;
                float v0 = acc[mt][nt][half * 2 + 0] + b0v[nt];
                float v1 = acc[mt][nt][half * 2 + 1] + b1v[nt];
                if (RELU) { v0 = fmaxf(v0, 0.f); v1 = fmaxf(v1, 0.f); }
                if (RES) {
                    float2 rr = *(const float2*)(res + (size_t)r * Nc + c);
                    v0 += rr.x; v1 += rr.y;
                }
                if (SPLITOUT) {
                    __nv_bfloat16 h0, h1, l0, l1;
                    split1(v0, h0, l0); split1(v1, h1, l1);
                    *(uint32_t*)(Chi + (size_t)r * Nc + c) = bpack(h0, h1);
                    *(uint32_t*)(Clo + (size_t)r * Nc + c) = bpack(l0, l1);
                } else {
                    *(float2*)(C + (size_t)r * Nc + c) = make_float2(v0, v1);
                }
            }
        }
    }
}

// ---------------- launch ----------------
extern "C" void kernel_launch(void* const* d_in, const int* in_sizes, int n_in,
                              void* d_out, int out_size) {
    const float* x      = (const float*)d_in[0];
    const int*   src    = (const int*)d_in[1];
    const int*   dst    = (const int*)d_in[2];
    const float* self_w = (const float*)d_in[3];
    const float* ppi_w  = (const float*)d_in[4];
    const float* W_in   = (const float*)d_in[5];
    const float* b_in   = (const float*)d_in[6];
    const float* W1     = (const float*)d_in[7];
    const float* b1     = (const float*)d_in[8];
    const float* W2     = (const float*)d_in[9];
    const float* b2     = (const float*)d_in[10];
    const float* W_out  = (const float*)d_in[11];
    const float* b_out  = (const float*)d_in[12];
    float* out = (float*)d_out;

    float *h, *res;
    __nv_bfloat16 *xhi, *xlo, *ahi, *alo, *hhi, *hlo;
    __nv_bfloat16 *winh, *winl, *w1h, *w1l, *w2h, *w2l, *woh, *wol;
    cudaGetSymbolAddress((void**)&h,    g_h);
    cudaGetSymbolAddress((void**)&res,  g_res);
    cudaGetSymbolAddress((void**)&xhi,  g_x_hi);
    cudaGetSymbolAddress((void**)&xlo,  g_x_lo);
    cudaGetSymbolAddress((void**)&ahi,  g_agg_hi);
    cudaGetSymbolAddress((void**)&alo,  g_agg_lo);
    cudaGetSymbolAddress((void**)&hhi,  g_h_hi);
    cudaGetSymbolAddress((void**)&hlo,  g_h_lo);
    cudaGetSymbolAddress((void**)&winh, g_win_hi);
    cudaGetSymbolAddress((void**)&winl, g_win_lo);
    cudaGetSymbolAddress((void**)&w1h,  g_w1_hi);
    cudaGetSymbolAddress((void**)&w1l,  g_w1_lo);
    cudaGetSymbolAddress((void**)&w2h,  g_w2_hi);
    cudaGetSymbolAddress((void**)&w2l,  g_w2_lo);
    cudaGetSymbolAddress((void**)&woh,  g_wout_hi);
    cudaGetSymbolAddress((void**)&wol,  g_wout_lo);

    cudaFuncSetAttribute(k_gemm_mma<true,  false, false>,
                         cudaFuncAttributeMaxDynamicSharedMemorySize, SMEM_GEMM);
    cudaFuncSetAttribute(k_gemm_mma<true,  true,  false>,
                         cudaFuncAttributeMaxDynamicSharedMemorySize, SMEM_GEMM);
    cudaFuncSetAttribute(k_gemm_mma<true,  true,  true>,
                         cudaFuncAttributeMaxDynamicSharedMemorySize, SMEM_GEMM);
    cudaFuncSetAttribute(k_gemm_mma<false, false, false>,
                         cudaFuncAttributeMaxDynamicSharedMemorySize, SMEM_GEMM);

    const long prep_items = (long)(N_NODES + 1) + (long)N_NODES * D_IN / 4
                          + (long)D_IN * D_H + 2L * D_H * D_H
                          + (long)D_H * N_LABELS;
    int prepBlocks = (int)((prep_items + 255) / 256);
    dim3 gNarrow(1, (N_NODES + 127) / 128);
    dim3 gOut((N_LABELS + 127) / 128, (N_NODES + 127) / 128);
    int aggBlocks = (N_NODES * 32 + 255) / 256;

    // ncu (empirically) profiles launch #4 -> input GEMM there.
    k_prep<<<prepBlocks, 256>>>(x, W_in, W1, W2, W_out);              // 1
    k_hist<<<(N_EDGES + 255) / 256, 256>>>(dst);                      // 2
    k_scan_fused<<<1, 1024>>>();                                      // 3
    k_gemm_mma<true, false, false><<<gNarrow, 256, SMEM_GEMM>>>(      // 4 (profiled)
        xhi, xlo, winh, winl, b_in, nullptr, h, nullptr, nullptr,
        N_NODES, D_IN, D_H);
    k_fill<<<(N_EDGES + 255) / 256, 256>>>(src, dst, self_w, ppi_w);  // 5

    k_aggregate<<<aggBlocks, 256>>>();                                // 6
    k_gemm_mma<true, true, false><<<gNarrow, 256, SMEM_GEMM>>>(       // 7
        ahi, alo, w1h, w1l, b1, res, h, nullptr, nullptr,
        N_NODES, D_H, D_H);
    k_aggregate<<<aggBlocks, 256>>>();                                // 8
    k_gemm_mma<true, true, true><<<gNarrow, 256, SMEM_GEMM>>>(        // 9
        ahi, alo, w2h, w2l, b2, res, nullptr, hhi, hlo,
        N_NODES, D_H, D_H);

    k_gemm_mma<false, false, false><<<gOut, 256, SMEM_GEMM>>>(        // 10
        hhi, hlo, woh, wol, b_out, nullptr, out, nullptr, nullptr,
        N_NODES, D_H, N_LABELS);
}

// round 9
// speedup vs baseline: 2.4359x; 1.0185x over previous
#include <cuda_runtime.h>
#include <cuda_bf16.h>
#include <cstdint>
#include <cstddef>

#define N_NODES 50000
#define N_EDGES 800000
#define D_IN    256
#define D_H     128
#define N_LABELS 1000

// ---------------- scratch (device globals: allocation-free) ----------------
__device__ float g_h[(size_t)N_NODES * D_H];
__device__ float g_res[(size_t)N_NODES * D_H];
__device__ __align__(16) int g_row_ptr[N_NODES + 4];
__device__ __align__(16) int g_cursor[N_NODES + 4];
__device__ float4 g_edata[N_EDGES];              // {src_as_float, self_w, ppi_w, 0}

// split-bf16 operands
__device__ __align__(16) __nv_bfloat16 g_x_hi[(size_t)N_NODES * D_IN];
__device__ __align__(16) __nv_bfloat16 g_x_lo[(size_t)N_NODES * D_IN];
__device__ __align__(16) __nv_bfloat16 g_agg_hi[(size_t)N_NODES * D_H];
__device__ __align__(16) __nv_bfloat16 g_agg_lo[(size_t)N_NODES * D_H];
__device__ __align__(16) __nv_bfloat16 g_h_hi[(size_t)N_NODES * D_H];
__device__ __align__(16) __nv_bfloat16 g_h_lo[(size_t)N_NODES * D_H];
// transposed weight splits: Wt[n][k]
__device__ __align__(16) __nv_bfloat16 g_win_hi[D_H * D_IN];
__device__ __align__(16) __nv_bfloat16 g_win_lo[D_H * D_IN];
__device__ __align__(16) __nv_bfloat16 g_w1_hi[D_H * D_H];
__device__ __align__(16) __nv_bfloat16 g_w1_lo[D_H * D_H];
__device__ __align__(16) __nv_bfloat16 g_w2_hi[D_H * D_H];
__device__ __align__(16) __nv_bfloat16 g_w2_lo[D_H * D_H];
__device__ __align__(16) __nv_bfloat16 g_wout_hi[(size_t)N_LABELS * D_H];
__device__ __align__(16) __nv_bfloat16 g_wout_lo[(size_t)N_LABELS * D_H];

// ---------------- helpers ----------------
__device__ __forceinline__ uint32_t smem_u32(const void* p) {
    uint32_t a;
    asm("{ .reg .u64 t; cvta.to.shared.u64 t, %1; cvt.u32.u64 %0, t; }"
        : "=r"(a) : "l"(p));
    return a;
}
__device__ __forceinline__ uint32_t bpack(__nv_bfloat16 a, __nv_bfloat16 b) {
    return (uint32_t)__bfloat16_as_ushort(a) |
           ((uint32_t)__bfloat16_as_ushort(b) << 16);
}
__device__ __forceinline__ void split1(float v, __nv_bfloat16& h, __nv_bfloat16& l) {
    h = __float2bfloat16_rn(v);
    l = __float2bfloat16_rn(v - __bfloat162float(h));
}
__device__ __forceinline__ void ldsm4(uint32_t* r, uint32_t addr) {
    asm volatile("ldmatrix.sync.aligned.m8n8.x4.shared.b16 {%0,%1,%2,%3}, [%4];"
        : "=r"(r[0]), "=r"(r[1]), "=r"(r[2]), "=r"(r[3]) : "r"(addr));
}
__device__ __forceinline__ void mma16816(float* d, const uint32_t* a, const uint32_t* b) {
    asm volatile("mma.sync.aligned.m16n8k16.row.col.f32.bf16.bf16.f32 "
        "{%0,%1,%2,%3}, {%4,%5,%6,%7}, {%8,%9}, {%0,%1,%2,%3};"
        : "+f"(d[0]), "+f"(d[1]), "+f"(d[2]), "+f"(d[3])
        : "r"(a[0]), "r"(a[1]), "r"(a[2]), "r"(a[3]), "r"(b[0]), "r"(b[1]));
}
__device__ __forceinline__ void cpasync16(uint32_t dst, const void* src, bool valid) {
    int sz = valid ? 16 : 0;
    asm volatile("cp.async.ca.shared.global [%0], [%1], 16, %2;"
        :: "r"(dst), "l"(src), "r"(sz) : "memory");
}
__device__ __forceinline__ void cp_commit() {
    asm volatile("cp.async.commit_group;" ::: "memory");
}
__device__ __forceinline__ void cp_wait0() {
    asm volatile("cp.async.wait_group 0;" ::: "memory");
}
__device__ __forceinline__ void cp_wait1() {
    asm volatile("cp.async.wait_group 1;" ::: "memory");
}

// ---------------- prep: zero rowptr + split x + split/transpose Ws ---------
__global__ void k_prep(const float* __restrict__ x, const float* __restrict__ Win,
                       const float* __restrict__ W1, const float* __restrict__ W2,
                       const float* __restrict__ Wout) {
    const long n0 = N_NODES + 1;
    const long n1 = n0 + (long)N_NODES * D_IN / 4;
    const long n2 = n1 + (long)D_IN * D_H;
    const long n3 = n2 + (long)D_H * D_H;
    const long n4 = n3 + (long)D_H * D_H;
    const long n5 = n4 + (long)D_H * N_LABELS;
    long idx = (long)blockIdx.x * blockDim.x + threadIdx.x;
    if (idx < n0) { g_row_ptr[idx] = 0; return; }
    if (idx < n1) {
        long i = (idx - n0) * 4;
        float4 v = *(const float4*)(x + i);
        __nv_bfloat16 h0, h1, h2, h3, l0, l1, l2, l3;
        split1(v.x, h0, l0); split1(v.y, h1, l1);
        split1(v.z, h2, l2); split1(v.w, h3, l3);
        *(uint2*)(g_x_hi + i) = make_uint2(bpack(h0, h1), bpack(h2, h3));
        *(uint2*)(g_x_lo + i) = make_uint2(bpack(l0, l1), bpack(l2, l3));
        return;
    }
    if (idx < n2) {
        long i = idx - n1; int n = (int)(i % D_H), k = (int)(i / D_H);
        __nv_bfloat16 h, l; split1(Win[(size_t)k * D_H + n], h, l);
        g_win_hi[(size_t)n * D_IN + k] = h; g_win_lo[(size_t)n * D_IN + k] = l;
        return;
    }
    if (idx < n3) {
        long i = idx - n2; int n = (int)(i % D_H), k = (int)(i / D_H);
        __nv_bfloat16 h, l; split1(W1[(size_t)k * D_H + n], h, l);
        g_w1_hi[(size_t)n * D_H + k] = h; g_w1_lo[(size_t)n * D_H + k] = l;
        return;
    }
    if (idx < n4) {
        long i = idx - n3; int n = (int)(i % D_H), k = (int)(i / D_H);
        __nv_bfloat16 h, l; split1(W2[(size_t)k * D_H + n], h, l);
        g_w2_hi[(size_t)n * D_H + k] = h; g_w2_lo[(size_t)n * D_H + k] = l;
        return;
    }
    if (idx < n5) {
        long i = idx - n4; int n = (int)(i % N_LABELS), k = (int)(i / N_LABELS);
        __nv_bfloat16 h, l; split1(Wout[(size_t)k * N_LABELS + n], h, l);
        g_wout_hi[(size_t)n * D_H + k] = h; g_wout_lo[(size_t)n * D_H + k] = l;
        return;
    }
}

// ---------------- CSR build ----------------
__global__ void k_hist(const int* __restrict__ dst) {
    int e = blockIdx.x * blockDim.x + threadIdx.x;
    if (e < N_EDGES) atomicAdd(&g_row_ptr[dst[e] + 1], 1);
}

__global__ void __launch_bounds__(1024) k_scan_fused() {
    __shared__ int warp_sums[32];
    __shared__ int carry_s;
    int tid = threadIdx.x, lane = tid & 31, wid = tid >> 5;
    if (tid == 0) carry_s = 0;
    __syncthreads();
    for (int base = 0; base <= N_NODES; base += 4096) {
        int i0 = base + tid * 4;
        int4 v = make_int4(0, 0, 0, 0);
        if (i0 + 3 <= N_NODES) {
            v = *(const int4*)&g_row_ptr[i0];
        } else if (i0 <= N_NODES) {
            v.x = g_row_ptr[i0];
            if (i0 + 1 <= N_NODES) v.y = g_row_ptr[i0 + 1];
            if (i0 + 2 <= N_NODES) v.z = g_row_ptr[i0 + 2];
        }
        int s1 = v.x, s2 = s1 + v.y, s3 = s2 + v.z, s4 = s3 + v.w;
        int x = s4;
        #pragma unroll
        for (int off = 1; off < 32; off <<= 1) {
            int t = __shfl_up_sync(0xffffffff, x, off);
            if (lane >= off) x += t;
        }
        if (lane == 31) warp_sums[wid] = x;
        __syncthreads();
        if (wid == 0) {
            int w = warp_sums[lane];
            #pragma unroll
            for (int off = 1; off < 32; off <<= 1) {
                int t = __shfl_up_sync(0xffffffff, w, off);
                if (lane >= off) w += t;
            }
            warp_sums[lane] = w;
        }
        __syncthreads();
        int carry = carry_s;
        int p = x - s4 + ((wid > 0) ? warp_sums[wid - 1] : 0) + carry;
        int o1 = p + s1, o2 = p + s2, o3 = p + s3, o4 = p + s4;
        if (i0 + 3 <= N_NODES) {
            *(int4*)&g_row_ptr[i0] = make_int4(o1, o2, o3, o4);
        } else if (i0 <= N_NODES) {
            g_row_ptr[i0] = o1;
            if (i0 + 1 <= N_NODES) g_row_ptr[i0 + 1] = o2;
            if (i0 + 2 <= N_NODES) g_row_ptr[i0 + 2] = o3;
        }
        if (i0 + 3 < N_NODES) {
            *(int4*)&g_cursor[i0] = make_int4(o1, o2, o3, o4);
        } else if (i0 < N_NODES) {
            g_cursor[i0] = o1;
            if (i0 + 1 < N_NODES) g_cursor[i0 + 1] = o2;
            if (i0 + 2 < N_NODES) g_cursor[i0 + 2] = o3;
            if (i0 + 3 < N_NODES) g_cursor[i0 + 3] = o4;
        }
        __syncthreads();
        if (tid == 0) carry_s = carry + warp_sums[31];
        __syncthreads();
    }
}

__global__ void k_fill(const int* __restrict__ src, const int* __restrict__ dst,
                       const float* __restrict__ sw, const float* __restrict__ pw) {
    int e = blockIdx.x * blockDim.x + threadIdx.x;
    if (e < N_EDGES) {
        int p = atomicAdd(&g_cursor[dst[e]], 1);
        float4 t;
        t.x = __int_as_float(src[e]);
        t.y = sw[e];
        t.z = pw[e];
        t.w = 0.f;
        g_edata[p] = t;
    }
}

// ---------------- aggregation: warp per node, 4-edge software pipeline -----
// Batches 4 edata loads (independent) then 4 independent gathers (MLP=4),
// then the FMAs — cuts exposed L2 latency per edge ~4x vs the serial chain.
__global__ void __launch_bounds__(256)
k_aggregate() {
    int warp = (blockIdx.x * blockDim.x + threadIdx.x) >> 5;
    int lane = threadIdx.x & 31;
    if (warp >= N_NODES) return;
    int beg = g_row_ptr[warp];
    int end = g_row_ptr[warp + 1];
    const float4* hb = (const float4*)g_h;
    float rx = 0.f, ry = 0.f, rz = 0.f, rw = 0.f;
    float ax = 0.f, ay = 0.f, az = 0.f, aw = 0.f;
    int i = beg;
    for (; i + 4 <= end; i += 4) {
        float4 t0 = __ldg(&g_edata[i + 0]);
        float4 t1 = __ldg(&g_edata[i + 1]);
        float4 t2 = __ldg(&g_edata[i + 2]);
        float4 t3 = __ldg(&g_edata[i + 3]);
        float4 v0 = __ldg(hb + (((size_t)__float_as_int(t0.x)) << 5) + lane);
        float4 v1 = __ldg(hb + (((size_t)__float_as_int(t1.x)) << 5) + lane);
        float4 v2 = __ldg(hb + (((size_t)__float_as_int(t2.x)) << 5) + lane);
        float4 v3 = __ldg(hb + (((size_t)__float_as_int(t3.x)) << 5) + lane);
        rx += t0.y * v0.x; ry += t0.y * v0.y; rz += t0.y * v0.z; rw += t0.y * v0.w;
        ax += t0.z * v0.x; ay += t0.z * v0.y; az += t0.z * v0.z; aw += t0.z * v0.w;
        rx += t1.y * v1.x; ry += t1.y * v1.y; rz += t1.y * v1.z; rw += t1.y * v1.w;
        ax += t1.z * v1.x; ay += t1.z * v1.y; az += t1.z * v1.z; aw += t1.z * v1.w;
        rx += t2.y * v2.x; ry += t2.y * v2.y; rz += t2.y * v2.z; rw += t2.y * v2.w;
        ax += t2.z * v2.x; ay += t2.z * v2.y; az += t2.z * v2.z; aw += t2.z * v2.w;
        rx += t3.y * v3.x; ry += t3.y * v3.y; rz += t3.y * v3.z; rw += t3.y * v3.w;
        ax += t3.z * v3.x; ay += t3.z * v3.y; az += t3.z * v3.z; aw += t3.z * v3.w;
    }
    for (; i < end; i++) {
        float4 t = __ldg(&g_edata[i]);
        float4 v = __ldg(hb + (((size_t)__float_as_int(t.x)) << 5) + lane);
        rx += t.y * v.x; ry += t.y * v.y; rz += t.y * v.z; rw += t.y * v.w;
        ax += t.z * v.x; ay += t.z * v.y; az += t.z * v.z; aw += t.z * v.w;
    }
    ((float4*)(g_res + (size_t)warp * D_H))[lane] = make_float4(rx, ry, rz, rw);
    __nv_bfloat16 h0, h1, h2, h3, l0, l1, l2, l3;
    split1(ax, h0, l0); split1(ay, h1, l1);
    split1(az, h2, l2); split1(aw, h3, l3);
    size_t o = (size_t)warp * D_H + lane * 4;
    *(uint2*)(g_agg_hi + o) = make_uint2(bpack(h0, h1), bpack(h2, h3));
    *(uint2*)(g_agg_lo + o) = make_uint2(bpack(l0, l1), bpack(l2, l3));
}

// ============================================================================
// split-bf16 GEMM on mma.sync.m16n8k16:  C = [relu](A@W + b) [+ res]
//   A split: Ahi/Alo [M,K] bf16 row-major. B split: Bhi/Blo = W^T [Nc,K].
//   D = Ahi·Bhi + Ahi·Blo + Alo·Bhi  (fp32 acc; dropped lo·lo <= 2^-18 rel).
//   CTA 128x128, 8 warps (4m x 2n), warp tile 32x64, K-chunk 32,
//   cp.async double buffer, 80B-pitch SMEM rows (conflict-free ldmatrix).
// ============================================================================
static constexpr int PITCH = 80;                 // 32 bf16 = 64B + 16B pad
static constexpr int BUF_A = 128 * PITCH;        // 10240 per matrix
static constexpr int OFF_AHI = 0;
static constexpr int OFF_ALO = BUF_A;
static constexpr int OFF_BHI = 2 * BUF_A;
static constexpr int OFF_BLO = 3 * BUF_A;
static constexpr int BUF_STRIDE = 4 * BUF_A;     // 40960
static constexpr int SMEM_GEMM = 2 * BUF_STRIDE; // 81920

template<bool RELU, bool RES, bool SPLITOUT>
__global__ void __launch_bounds__(256, 2)
k_gemm_mma(const __nv_bfloat16* __restrict__ Ahi, const __nv_bfloat16* __restrict__ Alo,
           const __nv_bfloat16* __restrict__ Bhi, const __nv_bfloat16* __restrict__ Blo,
           const float* __restrict__ bias, const float* __restrict__ res,
           float* __restrict__ C, __nv_bfloat16* __restrict__ Chi,
           __nv_bfloat16* __restrict__ Clo, int M, int K, int Nc) {
    extern __shared__ char smem[];
    uint32_t sb = smem_u32(smem);
    int tid = threadIdx.x, l = tid & 31, wid = tid >> 5;
    int brow = blockIdx.y * 128, bcol = blockIdx.x * 128;
    int mbase = (wid & 3) * 32;     // warp m offset
    int nbase = (wid >> 2) * 64;    // warp n offset

    float acc[2][8][4];
    #pragma unroll
    for (int a = 0; a < 2; a++)
        #pragma unroll
        for (int b = 0; b < 8; b++)
            #pragma unroll
            for (int c = 0; c < 4; c++) acc[a][b][c] = 0.f;

    int nCh = K >> 5;

    auto issue_copy = [&](int ch, int buf) {
        int k0 = ch * 32;
        uint32_t base = sb + buf * BUF_STRIDE;
        #pragma unroll
        for (int it = 0; it < 2; it++) {
            int idx = tid + it * 256;
            int row = idx >> 2, seg = idx & 3;
            uint32_t soff = row * PITCH + seg * 16;
            int gr = brow + row;
            bool va = gr < M;
            size_t aoff = (size_t)gr * K + k0 + seg * 8;
            cpasync16(base + OFF_AHI + soff, Ahi + aoff, va);
            cpasync16(base + OFF_ALO + soff, Alo + aoff, va);
            int gn = bcol + row;
            bool vb = gn < Nc;
            size_t boff = (size_t)gn * K + k0 + seg * 8;
            cpasync16(base + OFF_BHI + soff, Bhi + boff, vb);
            cpasync16(base + OFF_BLO + soff, Blo + boff, vb);
        }
        cp_commit();
    };

    issue_copy(0, 0);
    for (int ch = 0; ch < nCh; ch++) {
        int buf = ch & 1;
        if (ch + 1 < nCh) { issue_copy(ch + 1, buf ^ 1); cp_wait1(); }
        else cp_wait0();
        __syncthreads();

        uint32_t bA_hi = sb + buf * BUF_STRIDE + OFF_AHI;
        uint32_t bA_lo = sb + buf * BUF_STRIDE + OFF_ALO;
        uint32_t bB_hi = sb + buf * BUF_STRIDE + OFF_BHI;
        uint32_t bB_lo = sb + buf * BUF_STRIDE + OFF_BLO;

        #pragma unroll
        for (int ks = 0; ks < 2; ks++) {
            // A fragments: addr lanes 0-15 -> rows, col 0; 16-31 -> rows, col 8
            uint32_t aH[2][4], aL[2][4];
            #pragma unroll
            for (int mt = 0; mt < 2; mt++) {
                uint32_t ad = (uint32_t)((mbase + mt * 16 + (l & 15)) * PITCH
                                          + ks * 32 + (l >> 4) * 16);
                ldsm4(aH[mt], bA_hi + ad);
                ldsm4(aL[mt], bA_lo + ad);
            }
            #pragma unroll
            for (int np = 0; np < 4; np++) {
                // B x4: lanes 0-7 nt0/k0, 8-15 nt0/k8, 16-23 nt1/k0, 24-31 nt1/k8
                uint32_t nrow = (uint32_t)(nbase + np * 16 + (l & 7) + ((l >> 4) << 3));
                uint32_t bd = nrow * PITCH + ks * 32 + (((l >> 3) & 1) << 4);
                uint32_t bH[4], bL[4];
                ldsm4(bH, bB_hi + bd);
                ldsm4(bL, bB_lo + bd);
                #pragma unroll
                for (int mt = 0; mt < 2; mt++) {
                    mma16816(acc[mt][np * 2 + 0], aH[mt], bH + 0);
                    mma16816(acc[mt][np * 2 + 0], aH[mt], bL + 0);
                    mma16816(acc[mt][np * 2 + 0], aL[mt], bH + 0);
                    mma16816(acc[mt][np * 2 + 1], aH[mt], bH + 2);
                    mma16816(acc[mt][np * 2 + 1], aH[mt], bL + 2);
                    mma16816(acc[mt][np * 2 + 1], aL[mt], bH + 2);
                }
            }
        }
        __syncthreads();
    }

    // epilogue: lane l holds (row = l/4 [+8], cols = 2*(l%4)+{0,1}) per tile
    int rl = l >> 2;
    int cq = (l & 3) * 2;
    float b0v[8], b1v[8];
    bool cok[8];
    #pragma unroll
    for (int nt = 0; nt < 8; nt++) {
        int c = bcol + nbase + nt * 8 + cq;
        cok[nt] = c < Nc;
        b0v[nt] = cok[nt] ? bias[c] : 0.f;
        b1v[nt] = cok[nt] ? bias[c + 1] : 0.f;
    }
    #pragma unroll
    for (int mt = 0; mt < 2; mt++) {
        #pragma unroll
        for (int half = 0; half < 2; half++) {
            int r = brow + mbase + mt * 16 + rl + half * 8;
            if (r >= M) continue;
            #pragma unroll
            for (int nt = 0; nt < 8; nt++) {
                if (!cok[nt]) continue;
                int c = bcol + nbase + nt * 8 + cq;
                float v0 = acc[mt][nt][half * 2 + 0] + b0v[nt];
                float v1 = acc[mt][nt][half * 2 + 1] + b1v[nt];
                if (RELU) { v0 = fmaxf(v0, 0.f); v1 = fmaxf(v1, 0.f); }
                if (RES) {
                    float2 rr = *(const float2*)(res + (size_t)r * Nc + c);
                    v0 += rr.x; v1 += rr.y;
                }
                if (SPLITOUT) {
                    __nv_bfloat16 h0, h1, l0, l1;
                    split1(v0, h0, l0); split1(v1, h1, l1);
                    *(uint32_t*)(Chi + (size_t)r * Nc + c) = bpack(h0, h1);
                    *(uint32_t*)(Clo + (size_t)r * Nc + c) = bpack(l0, l1);
                } else {
                    *(float2*)(C + (size_t)r * Nc + c) = make_float2(v0, v1);
                }
            }
        }
    }
}

// ---------------- launch ----------------
extern "C" void kernel_launch(void* const* d_in, const int* in_sizes, int n_in,
                              void* d_out, int out_size) {
    const float* x      = (const float*)d_in[0];
    const int*   src    = (const int*)d_in[1];
    const int*   dst    = (const int*)d_in[2];
    const float* self_w = (const float*)d_in[3];
    const float* ppi_w  = (const float*)d_in[4];
    const float* W_in   = (const float*)d_in[5];
    const float* b_in   = (const float*)d_in[6];
    const float* W1     = (const float*)d_in[7];
    const float* b1     = (const float*)d_in[8];
    const float* W2     = (const float*)d_in[9];
    const float* b2     = (const float*)d_in[10];
    const float* W_out  = (const float*)d_in[11];
    const float* b_out  = (const float*)d_in[12];
    float* out = (float*)d_out;

    float *h, *res;
    __nv_bfloat16 *xhi, *xlo, *ahi, *alo, *hhi, *hlo;
    __nv_bfloat16 *winh, *winl, *w1h, *w1l, *w2h, *w2l, *woh, *wol;
    cudaGetSymbolAddress((void**)&h,    g_h);
    cudaGetSymbolAddress((void**)&res,  g_res);
    cudaGetSymbolAddress((void**)&xhi,  g_x_hi);
    cudaGetSymbolAddress((void**)&xlo,  g_x_lo);
    cudaGetSymbolAddress((void**)&ahi,  g_agg_hi);
    cudaGetSymbolAddress((void**)&alo,  g_agg_lo);
    cudaGetSymbolAddress((void**)&hhi,  g_h_hi);
    cudaGetSymbolAddress((void**)&hlo,  g_h_lo);
    cudaGetSymbolAddress((void**)&winh, g_win_hi);
    cudaGetSymbolAddress((void**)&winl, g_win_lo);
    cudaGetSymbolAddress((void**)&w1h,  g_w1_hi);
    cudaGetSymbolAddress((void**)&w1l,  g_w1_lo);
    cudaGetSymbolAddress((void**)&w2h,  g_w2_hi);
    cudaGetSymbolAddress((void**)&w2l,  g_w2_lo);
    cudaGetSymbolAddress((void**)&woh,  g_wout_hi);
    cudaGetSymbolAddress((void**)&wol,  g_wout_lo);

    cudaFuncSetAttribute(k_gemm_mma<true,  false, false>,
                         cudaFuncAttributeMaxDynamicSharedMemorySize, SMEM_GEMM);
    cudaFuncSetAttribute(k_gemm_mma<true,  true,  false>,
                         cudaFuncAttributeMaxDynamicSharedMemorySize, SMEM_GEMM);
    cudaFuncSetAttribute(k_gemm_mma<true,  true,  true>,
                         cudaFuncAttributeMaxDynamicSharedMemorySize, SMEM_GEMM);
    cudaFuncSetAttribute(k_gemm_mma<false, false, false>,
                         cudaFuncAttributeMaxDynamicSharedMemorySize, SMEM_GEMM);

    const long prep_items = (long)(N_NODES + 1) + (long)N_NODES * D_IN / 4
                          + (long)D_IN * D_H + 2L * D_H * D_H
                          + (long)D_H * N_LABELS;
    int prepBlocks = (int)((prep_items + 255) / 256);
    dim3 gNarrow(1, (N_NODES + 127) / 128);
    dim3 gOut((N_LABELS + 127) / 128, (N_NODES + 127) / 128);
    int aggBlocks = (N_NODES * 32 + 255) / 256;

    // ncu (empirically) profiles launch #4 -> input GEMM there.
    k_prep<<<prepBlocks, 256>>>(x, W_in, W1, W2, W_out);              // 1
    k_hist<<<(N_EDGES + 255) / 256, 256>>>(dst);                      // 2
    k_scan_fused<<<1, 1024>>>();                                      // 3
    k_gemm_mma<true, false, false><<<gNarrow, 256, SMEM_GEMM>>>(      // 4 (profiled)
        xhi, xlo, winh, winl, b_in, nullptr, h, nullptr, nullptr,
        N_NODES, D_IN, D_H);
    k_fill<<<(N_EDGES + 255) / 256, 256>>>(src, dst, self_w, ppi_w);  // 5

    k_aggregate<<<aggBlocks, 256>>>();                                // 6
    k_gemm_mma<true, true, false><<<gNarrow, 256, SMEM_GEMM>>>(       // 7
        ahi, alo, w1h, w1l, b1, res, h, nullptr, nullptr,
        N_NODES, D_H, D_H);
    k_aggregate<<<aggBlocks, 256>>>();                                // 8
    k_gemm_mma<true, true, true><<<gNarrow, 256, SMEM_GEMM>>>(        // 9
        ahi, alo, w2h, w2l, b2, res, nullptr, hhi, hlo,
        N_NODES, D_H, D_H);

    k_gemm_mma<false, false, false><<<gOut, 256, SMEM_GEMM>>>(        // 10
        hhi, hlo, woh, wol, b_out, nullptr, out, nullptr, nullptr,
        N_NODES, D_H, N_LABELS);
}

// round 10
// speedup vs baseline: 2.4456x; 1.0040x over previous
#include <cuda_runtime.h>
#include <cuda_bf16.h>
#include <cstdint>
#include <cstddef>

#define N_NODES 50000
#define N_EDGES 800000
#define D_IN    256
#define D_H     128
#define N_LABELS 1000

// ---------------- scratch (device globals: allocation-free) ----------------
__device__ float g_h[(size_t)N_NODES * D_H];
__device__ float g_res[(size_t)N_NODES * D_H];
__device__ __align__(16) int g_row_ptr[N_NODES + 4];
__device__ __align__(16) int g_cursor[N_NODES + 4];
__device__ float4 g_edata[N_EDGES];              // {src_as_float, self_w, ppi_w, 0}

// split-bf16 operands
__device__ __align__(16) __nv_bfloat16 g_x_hi[(size_t)N_NODES * D_IN];
__device__ __align__(16) __nv_bfloat16 g_x_lo[(size_t)N_NODES * D_IN];
__device__ __align__(16) __nv_bfloat16 g_agg_hi[(size_t)N_NODES * D_H];
__device__ __align__(16) __nv_bfloat16 g_agg_lo[(size_t)N_NODES * D_H];
__device__ __align__(16) __nv_bfloat16 g_h_hi[(size_t)N_NODES * D_H];
__device__ __align__(16) __nv_bfloat16 g_h_lo[(size_t)N_NODES * D_H];
// transposed weight splits: Wt[n][k]
__device__ __align__(16) __nv_bfloat16 g_win_hi[D_H * D_IN];
__device__ __align__(16) __nv_bfloat16 g_win_lo[D_H * D_IN];
__device__ __align__(16) __nv_bfloat16 g_w1_hi[D_H * D_H];
__device__ __align__(16) __nv_bfloat16 g_w1_lo[D_H * D_H];
__device__ __align__(16) __nv_bfloat16 g_w2_hi[D_H * D_H];
__device__ __align__(16) __nv_bfloat16 g_w2_lo[D_H * D_H];
__device__ __align__(16) __nv_bfloat16 g_wout_hi[(size_t)N_LABELS * D_H];
__device__ __align__(16) __nv_bfloat16 g_wout_lo[(size_t)N_LABELS * D_H];

// ---------------- helpers ----------------
__device__ __forceinline__ uint32_t smem_u32(const void* p) {
    uint32_t a;
    asm("{ .reg .u64 t; cvta.to.shared.u64 t, %1; cvt.u32.u64 %0, t; }"
        : "=r"(a) : "l"(p));
    return a;
}
__device__ __forceinline__ uint32_t bpack(__nv_bfloat16 a, __nv_bfloat16 b) {
    return (uint32_t)__bfloat16_as_ushort(a) |
           ((uint32_t)__bfloat16_as_ushort(b) << 16);
}
__device__ __forceinline__ void split1(float v, __nv_bfloat16& h, __nv_bfloat16& l) {
    h = __float2bfloat16_rn(v);
    l = __float2bfloat16_rn(v - __bfloat162float(h));
}
__device__ __forceinline__ void ldsm4(uint32_t* r, uint32_t addr) {
    asm volatile("ldmatrix.sync.aligned.m8n8.x4.shared.b16 {%0,%1,%2,%3}, [%4];"
        : "=r"(r[0]), "=r"(r[1]), "=r"(r[2]), "=r"(r[3]) : "r"(addr));
}
__device__ __forceinline__ void mma16816(float* d, const uint32_t* a, const uint32_t* b) {
    asm volatile("mma.sync.aligned.m16n8k16.row.col.f32.bf16.bf16.f32 "
        "{%0,%1,%2,%3}, {%4,%5,%6,%7}, {%8,%9}, {%0,%1,%2,%3};"
        : "+f"(d[0]), "+f"(d[1]), "+f"(d[2]), "+f"(d[3])
        : "r"(a[0]), "r"(a[1]), "r"(a[2]), "r"(a[3]), "r"(b[0]), "r"(b[1]));
}
__device__ __forceinline__ void cpasync16(uint32_t dst, const void* src, bool valid) {
    int sz = valid ? 16 : 0;
    asm volatile("cp.async.ca.shared.global [%0], [%1], 16, %2;"
        :: "r"(dst), "l"(src), "r"(sz) : "memory");
}
__device__ __forceinline__ void cp_commit() {
    asm volatile("cp.async.commit_group;" ::: "memory");
}
__device__ __forceinline__ void cp_wait0() {
    asm volatile("cp.async.wait_group 0;" ::: "memory");
}
__device__ __forceinline__ void cp_wait1() {
    asm volatile("cp.async.wait_group 1;" ::: "memory");
}

// ---------------- prep: zero rowptr + split x + split/transpose Ws ---------
__global__ void k_prep(const float* __restrict__ x, const float* __restrict__ Win,
                       const float* __restrict__ W1, const float* __restrict__ W2,
                       const float* __restrict__ Wout) {
    const long n0 = N_NODES + 1;
    const long n1 = n0 + (long)N_NODES * D_IN / 4;
    const long n2 = n1 + (long)D_IN * D_H;
    const long n3 = n2 + (long)D_H * D_H;
    const long n4 = n3 + (long)D_H * D_H;
    const long n5 = n4 + (long)D_H * N_LABELS;
    long idx = (long)blockIdx.x * blockDim.x + threadIdx.x;
    if (idx < n0) { g_row_ptr[idx] = 0; return; }
    if (idx < n1) {
        long i = (idx - n0) * 4;
        float4 v = *(const float4*)(x + i);
        __nv_bfloat16 h0, h1, h2, h3, l0, l1, l2, l3;
        split1(v.x, h0, l0); split1(v.y, h1, l1);
        split1(v.z, h2, l2); split1(v.w, h3, l3);
        *(uint2*)(g_x_hi + i) = make_uint2(bpack(h0, h1), bpack(h2, h3));
        *(uint2*)(g_x_lo + i) = make_uint2(bpack(l0, l1), bpack(l2, l3));
        return;
    }
    if (idx < n2) {
        long i = idx - n1; int n = (int)(i % D_H), k = (int)(i / D_H);
        __nv_bfloat16 h, l; split1(Win[(size_t)k * D_H + n], h, l);
        g_win_hi[(size_t)n * D_IN + k] = h; g_win_lo[(size_t)n * D_IN + k] = l;
        return;
    }
    if (idx < n3) {
        long i = idx - n2; int n = (int)(i % D_H), k = (int)(i / D_H);
        __nv_bfloat16 h, l; split1(W1[(size_t)k * D_H + n], h, l);
        g_w1_hi[(size_t)n * D_H + k] = h; g_w1_lo[(size_t)n * D_H + k] = l;
        return;
    }
    if (idx < n4) {
        long i = idx - n3; int n = (int)(i % D_H), k = (int)(i / D_H);
        __nv_bfloat16 h, l; split1(W2[(size_t)k * D_H + n], h, l);
        g_w2_hi[(size_t)n * D_H + k] = h; g_w2_lo[(size_t)n * D_H + k] = l;
        return;
    }
    if (idx < n5) {
        long i = idx - n4; int n = (int)(i % N_LABELS), k = (int)(i / N_LABELS);
        __nv_bfloat16 h, l; split1(Wout[(size_t)k * N_LABELS + n], h, l);
        g_wout_hi[(size_t)n * D_H + k] = h; g_wout_lo[(size_t)n * D_H + k] = l;
        return;
    }
}

// ---------------- CSR build ----------------
__global__ void k_hist(const int* __restrict__ dst) {
    int e = blockIdx.x * blockDim.x + threadIdx.x;
    if (e < N_EDGES) atomicAdd(&g_row_ptr[dst[e] + 1], 1);
}

__global__ void __launch_bounds__(1024) k_scan_fused() {
    __shared__ int warp_sums[32];
    __shared__ int carry_s;
    int tid = threadIdx.x, lane = tid & 31, wid = tid >> 5;
    if (tid == 0) carry_s = 0;
    __syncthreads();
    for (int base = 0; base <= N_NODES; base += 4096) {
        int i0 = base + tid * 4;
        int4 v = make_int4(0, 0, 0, 0);
        if (i0 + 3 <= N_NODES) {
            v = *(const int4*)&g_row_ptr[i0];
        } else if (i0 <= N_NODES) {
            v.x = g_row_ptr[i0];
            if (i0 + 1 <= N_NODES) v.y = g_row_ptr[i0 + 1];
            if (i0 + 2 <= N_NODES) v.z = g_row_ptr[i0 + 2];
        }
        int s1 = v.x, s2 = s1 + v.y, s3 = s2 + v.z, s4 = s3 + v.w;
        int x = s4;
        #pragma unroll
        for (int off = 1; off < 32; off <<= 1) {
            int t = __shfl_up_sync(0xffffffff, x, off);
            if (lane >= off) x += t;
        }
        if (lane == 31) warp_sums[wid] = x;
        __syncthreads();
        if (wid == 0) {
            int w = warp_sums[lane];
            #pragma unroll
            for (int off = 1; off < 32; off <<= 1) {
                int t = __shfl_up_sync(0xffffffff, w, off);
                if (lane >= off) w += t;
            }
            warp_sums[lane] = w;
        }
        __syncthreads();
        int carry = carry_s;
        int p = x - s4 + ((wid > 0) ? warp_sums[wid - 1] : 0) + carry;
        int o1 = p + s1, o2 = p + s2, o3 = p + s3, o4 = p + s4;
        if (i0 + 3 <= N_NODES) {
            *(int4*)&g_row_ptr[i0] = make_int4(o1, o2, o3, o4);
        } else if (i0 <= N_NODES) {
            g_row_ptr[i0] = o1;
            if (i0 + 1 <= N_NODES) g_row_ptr[i0 + 1] = o2;
            if (i0 + 2 <= N_NODES) g_row_ptr[i0 + 2] = o3;
        }
        if (i0 + 3 < N_NODES) {
            *(int4*)&g_cursor[i0] = make_int4(o1, o2, o3, o4);
        } else if (i0 < N_NODES) {
            g_cursor[i0] = o1;
            if (i0 + 1 < N_NODES) g_cursor[i0 + 1] = o2;
            if (i0 + 2 < N_NODES) g_cursor[i0 + 2] = o3;
            if (i0 + 3 < N_NODES) g_cursor[i0 + 3] = o4;
        }
        __syncthreads();
        if (tid == 0) carry_s = carry + warp_sums[31];
        __syncthreads();
    }
}

__global__ void k_fill(const int* __restrict__ src, const int* __restrict__ dst,
                       const float* __restrict__ sw, const float* __restrict__ pw) {
    int e = blockIdx.x * blockDim.x + threadIdx.x;
    if (e < N_EDGES) {
        int p = atomicAdd(&g_cursor[dst[e]], 1);
        float4 t;
        t.x = __int_as_float(src[e]);
        t.y = sw[e];
        t.z = pw[e];
        t.w = 0.f;
        g_edata[p] = t;
    }
}

// ---------------- aggregation: warp per node, 4-edge software pipeline -----
__global__ void __launch_bounds__(256)
k_aggregate() {
    int warp = (blockIdx.x * blockDim.x + threadIdx.x) >> 5;
    int lane = threadIdx.x & 31;
    if (warp >= N_NODES) return;
    int beg = g_row_ptr[warp];
    int end = g_row_ptr[warp + 1];
    const float4* hb = (const float4*)g_h;
    float rx = 0.f, ry = 0.f, rz = 0.f, rw = 0.f;
    float ax = 0.f, ay = 0.f, az = 0.f, aw = 0.f;
    int i = beg;
    for (; i + 4 <= end; i += 4) {
        float4 t0 = __ldg(&g_edata[i + 0]);
        float4 t1 = __ldg(&g_edata[i + 1]);
        float4 t2 = __ldg(&g_edata[i + 2]);
        float4 t3 = __ldg(&g_edata[i + 3]);
        float4 v0 = __ldg(hb + (((size_t)__float_as_int(t0.x)) << 5) + lane);
        float4 v1 = __ldg(hb + (((size_t)__float_as_int(t1.x)) << 5) + lane);
        float4 v2 = __ldg(hb + (((size_t)__float_as_int(t2.x)) << 5) + lane);
        float4 v3 = __ldg(hb + (((size_t)__float_as_int(t3.x)) << 5) + lane);
        rx += t0.y * v0.x; ry += t0.y * v0.y; rz += t0.y * v0.z; rw += t0.y * v0.w;
        ax += t0.z * v0.x; ay += t0.z * v0.y; az += t0.z * v0.z; aw += t0.z * v0.w;
        rx += t1.y * v1.x; ry += t1.y * v1.y; rz += t1.y * v1.z; rw += t1.y * v1.w;
        ax += t1.z * v1.x; ay += t1.z * v1.y; az += t1.z * v1.z; aw += t1.z * v1.w;
        rx += t2.y * v2.x; ry += t2.y * v2.y; rz += t2.y * v2.z; rw += t2.y * v2.w;
        ax += t2.z * v2.x; ay += t2.z * v2.y; az += t2.z * v2.z; aw += t2.z * v2.w;
        rx += t3.y * v3.x; ry += t3.y * v3.y; rz += t3.y * v3.z; rw += t3.y * v3.w;
        ax += t3.z * v3.x; ay += t3.z * v3.y; az += t3.z * v3.z; aw += t3.z * v3.w;
    }
    for (; i < end; i++) {
        float4 t = __ldg(&g_edata[i]);
        float4 v = __ldg(hb + (((size_t)__float_as_int(t.x)) << 5) + lane);
        rx += t.y * v.x; ry += t.y * v.y; rz += t.y * v.z; rw += t.y * v.w;
        ax += t.z * v.x; ay += t.z * v.y; az += t.z * v.z; aw += t.z * v.w;
    }
    ((float4*)(g_res + (size_t)warp * D_H))[lane] = make_float4(rx, ry, rz, rw);
    __nv_bfloat16 h0, h1, h2, h3, l0, l1, l2, l3;
    split1(ax, h0, l0); split1(ay, h1, l1);
    split1(az, h2, l2); split1(aw, h3, l3);
    size_t o = (size_t)warp * D_H + lane * 4;
    *(uint2*)(g_agg_hi + o) = make_uint2(bpack(h0, h1), bpack(h2, h3));
    *(uint2*)(g_agg_lo + o) = make_uint2(bpack(l0, l1), bpack(l2, l3));
}

// ============================================================================
// split-bf16 GEMM on mma.sync.m16n8k16:  C = [relu](A@W + b) [+ res]
//   A split: Ahi/Alo [M,K] bf16 row-major. B split: Bhi/Blo = W^T [Nc,K].
//   D = Ahi·Bhi + Ahi·Blo + Alo·Bhi  (fp32 acc; dropped lo·lo <= 2^-18 rel).
//   CTA 128x128, 8 warps (4m x 2n), warp tile 32x64, K-chunk 32,
//   cp.async double buffer, 80B-pitch SMEM rows (conflict-free ldmatrix).
//   Inner loop software-pipelines B-fragment ldmatrix against the MMAs
//   (double-buffered bH/bL) so the LDS and tensor pipes overlap instead of
//   ping-ponging (R9 profile: tensor 44% + L1 49% ~ mutually exclusive).
// ============================================================================
static constexpr int PITCH = 80;                 // 32 bf16 = 64B + 16B pad
static constexpr int BUF_A = 128 * PITCH;        // 10240 per matrix
static constexpr int OFF_AHI = 0;
static constexpr int OFF_ALO = BUF_A;
static constexpr int OFF_BHI = 2 * BUF_A;
static constexpr int OFF_BLO = 3 * BUF_A;
static constexpr int BUF_STRIDE = 4 * BUF_A;     // 40960
static constexpr int SMEM_GEMM = 2 * BUF_STRIDE; // 81920

template<bool RELU, bool RES, bool SPLITOUT>
__global__ void __launch_bounds__(256, 2)
k_gemm_mma(const __nv_bfloat16* __restrict__ Ahi, const __nv_bfloat16* __restrict__ Alo,
           const __nv_bfloat16* __restrict__ Bhi, const __nv_bfloat16* __restrict__ Blo,
           const float* __restrict__ bias, const float* __restrict__ res,
           float* __restrict__ C, __nv_bfloat16* __restrict__ Chi,
           __nv_bfloat16* __restrict__ Clo, int M, int K, int Nc) {
    extern __shared__ char smem[];
    uint32_t sb = smem_u32(smem);
    int tid = threadIdx.x, l = tid & 31, wid = tid >> 5;
    int brow = blockIdx.y * 128, bcol = blockIdx.x * 128;
    int mbase = (wid & 3) * 32;     // warp m offset
    int nbase = (wid >> 2) * 64;    // warp n offset

    float acc[2][8][4];
    #pragma unroll
    for (int a = 0; a < 2; a++)
        #pragma unroll
        for (int b = 0; b < 8; b++)
            #pragma unroll
            for (int c = 0; c < 4; c++) acc[a][b][c] = 0.f;

    int nCh = K >> 5;

    auto issue_copy = [&](int ch, int buf) {
        int k0 = ch * 32;
        uint32_t base = sb + buf * BUF_STRIDE;
        #pragma unroll
        for (int it = 0; it < 2; it++) {
            int idx = tid + it * 256;
            int row = idx >> 2, seg = idx & 3;
            uint32_t soff = row * PITCH + seg * 16;
            int gr = brow + row;
            bool va = gr < M;
            size_t aoff = (size_t)gr * K + k0 + seg * 8;
            cpasync16(base + OFF_AHI + soff, Ahi + aoff, va);
            cpasync16(base + OFF_ALO + soff, Alo + aoff, va);
            int gn = bcol + row;
            bool vb = gn < Nc;
            size_t boff = (size_t)gn * K + k0 + seg * 8;
            cpasync16(base + OFF_BHI + soff, Bhi + boff, vb);
            cpasync16(base + OFF_BLO + soff, Blo + boff, vb);
        }
        cp_commit();
    };

    // precomputed per-thread ldmatrix address components
    uint32_t a_lane_off = (uint32_t)((l & 15) * PITCH + (l >> 4) * 16);
    uint32_t b_lane_row = (uint32_t)((l & 7) + ((l >> 4) << 3));
    uint32_t b_lane_k   = (uint32_t)((((l >> 3) & 1) << 4));

    issue_copy(0, 0);
    for (int ch = 0; ch < nCh; ch++) {
        int buf = ch & 1;
        if (ch + 1 < nCh) { issue_copy(ch + 1, buf ^ 1); cp_wait1(); }
        else cp_wait0();
        __syncthreads();

        uint32_t bA_hi = sb + buf * BUF_STRIDE + OFF_AHI;
        uint32_t bA_lo = sb + buf * BUF_STRIDE + OFF_ALO;
        uint32_t bB_hi = sb + buf * BUF_STRIDE + OFF_BHI;
        uint32_t bB_lo = sb + buf * BUF_STRIDE + OFF_BLO;

        #pragma unroll
        for (int ks = 0; ks < 2; ks++) {
            // A fragments for this ks (both split halves)
            uint32_t aH[2][4], aL[2][4];
            #pragma unroll
            for (int mt = 0; mt < 2; mt++) {
                uint32_t ad = (uint32_t)((mbase + mt * 16) * PITCH + ks * 32)
                              + a_lane_off;
                ldsm4(aH[mt], bA_hi + ad);
                ldsm4(aL[mt], bA_lo + ad);
            }
            // B fragments: double-buffered np-pipeline so ldmatrix(np+1)
            // is in flight while the MMAs of np execute.
            uint32_t bH[2][4], bL[2][4];
            {
                uint32_t bd = (nbase + b_lane_row) * PITCH + ks * 32 + b_lane_k;
                ldsm4(bH[0], bB_hi + bd);
                ldsm4(bL[0], bB_lo + bd);
            }
            #pragma unroll
            for (int np = 0; np < 4; np++) {
                int cur = np & 1;
                if (np < 3) {
                    int nxt = cur ^ 1;
                    uint32_t bd = (nbase + (np + 1) * 16 + b_lane_row) * PITCH
                                  + ks * 32 + b_lane_k;
                    ldsm4(bH[nxt], bB_hi + bd);
                    ldsm4(bL[nxt], bB_lo + bd);
                }
                #pragma unroll
                for (int mt = 0; mt < 2; mt++) {
                    mma16816(acc[mt][np * 2 + 0], aH[mt], bH[cur] + 0);
                    mma16816(acc[mt][np * 2 + 0], aH[mt], bL[cur] + 0);
                    mma16816(acc[mt][np * 2 + 0], aL[mt], bH[cur] + 0);
                    mma16816(acc[mt][np * 2 + 1], aH[mt], bH[cur] + 2);
                    mma16816(acc[mt][np * 2 + 1], aH[mt], bL[cur] + 2);
                    mma16816(acc[mt][np * 2 + 1], aL[mt], bH[cur] + 2);
                }
            }
        }
        __syncthreads();
    }

    // epilogue: lane l holds (row = l/4 [+8], cols = 2*(l%4)+{0,1}) per tile
    int rl = l >> 2;
    int cq = (l & 3) * 2;
    float b0v[8], b1v[8];
    bool cok[8];
    #pragma unroll
    for (int nt = 0; nt < 8; nt++) {
        int c = bcol + nbase + nt * 8 + cq;
        cok[nt] = c < Nc;
        b0v[nt] = cok[nt] ? bias[c] : 0.f;
        b1v[nt] = cok[nt] ? bias[c + 1] : 0.f;
    }
    #pragma unroll
    for (int mt = 0; mt < 2; mt++) {
        #pragma unroll
        for (int half = 0; half < 2; half++) {
            int r = brow + mbase + mt * 16 + rl + half * 8;
            if (r >= M) continue;
            #pragma unroll
            for (int nt = 0; nt < 8; nt++) {
                if (!cok[nt]) continue;
                int c = bcol + nbase + nt * 8 + cq;
                float v0 = acc[mt][nt][half * 2 + 0] + b0v[nt];
                float v1 = acc[mt][nt][half * 2 + 1] + b1v[nt];
                if (RELU) { v0 = fmaxf(v0, 0.f); v1 = fmaxf(v1, 0.f); }
                if (RES) {
                    float2 rr = *(const float2*)(res + (size_t)r * Nc + c);
                    v0 += rr.x; v1 += rr.y;
                }
                if (SPLITOUT) {
                    __nv_bfloat16 h0, h1, l0, l1;
                    split1(v0, h0, l0); split1(v1, h1, l1);
                    *(uint32_t*)(Chi + (size_t)r * Nc + c) = bpack(h0, h1);
                    *(uint32_t*)(Clo + (size_t)r * Nc + c) = bpack(l0, l1);
                } else {
                    *(float2*)(C + (size_t)r * Nc + c) = make_float2(v0, v1);
                }
            }
        }
    }
}

// ---------------- launch ----------------
extern "C" void kernel_launch(void* const* d_in, const int* in_sizes, int n_in,
                              void* d_out, int out_size) {
    const float* x      = (const float*)d_in[0];
    const int*   src    = (const int*)d_in[1];
    const int*   dst    = (const int*)d_in[2];
    const float* self_w = (const float*)d_in[3];
    const float* ppi_w  = (const float*)d_in[4];
    const float* W_in   = (const float*)d_in[5];
    const float* b_in   = (const float*)d_in[6];
    const float* W1     = (const float*)d_in[7];
    const float* b1     = (const float*)d_in[8];
    const float* W2     = (const float*)d_in[9];
    const float* b2     = (const float*)d_in[10];
    const float* W_out  = (const float*)d_in[11];
    const float* b_out  = (const float*)d_in[12];
    float* out = (float*)d_out;

    float *h, *res;
    __nv_bfloat16 *xhi, *xlo, *ahi, *alo, *hhi, *hlo;
    __nv_bfloat16 *winh, *winl, *w1h, *w1l, *w2h, *w2l, *woh, *wol;
    cudaGetSymbolAddress((void**)&h,    g_h);
    cudaGetSymbolAddress((void**)&res,  g_res);
    cudaGetSymbolAddress((void**)&xhi,  g_x_hi);
    cudaGetSymbolAddress((void**)&xlo,  g_x_lo);
    cudaGetSymbolAddress((void**)&ahi,  g_agg_hi);
    cudaGetSymbolAddress((void**)&alo,  g_agg_lo);
    cudaGetSymbolAddress((void**)&hhi,  g_h_hi);
    cudaGetSymbolAddress((void**)&hlo,  g_h_lo);
    cudaGetSymbolAddress((void**)&winh, g_win_hi);
    cudaGetSymbolAddress((void**)&winl, g_win_lo);
    cudaGetSymbolAddress((void**)&w1h,  g_w1_hi);
    cudaGetSymbolAddress((void**)&w1l,  g_w1_lo);
    cudaGetSymbolAddress((void**)&w2h,  g_w2_hi);
    cudaGetSymbolAddress((void**)&w2l,  g_w2_lo);
    cudaGetSymbolAddress((void**)&woh,  g_wout_hi);
    cudaGetSymbolAddress((void**)&wol,  g_wout_lo);

    cudaFuncSetAttribute(k_gemm_mma<true,  false, false>,
                         cudaFuncAttributeMaxDynamicSharedMemorySize, SMEM_GEMM);
    cudaFuncSetAttribute(k_gemm_mma<true,  true,  false>,
                         cudaFuncAttributeMaxDynamicSharedMemorySize, SMEM_GEMM);
    cudaFuncSetAttribute(k_gemm_mma<true,  true,  true>,
                         cudaFuncAttributeMaxDynamicSharedMemorySize, SMEM_GEMM);
    cudaFuncSetAttribute(k_gemm_mma<false, false, false>,
                         cudaFuncAttributeMaxDynamicSharedMemorySize, SMEM_GEMM);

    const long prep_items = (long)(N_NODES + 1) + (long)N_NODES * D_IN / 4
                          + (long)D_IN * D_H + 2L * D_H * D_H
                          + (long)D_H * N_LABELS;
    int prepBlocks = (int)((prep_items + 255) / 256);
    dim3 gNarrow(1, (N_NODES + 127) / 128);
    dim3 gOut((N_LABELS + 127) / 128, (N_NODES + 127) / 128);
    int aggBlocks = (N_NODES * 32 + 255) / 256;

    // ncu (empirically) profiles launch #4 -> input GEMM there.
    k_prep<<<prepBlocks, 256>>>(x, W_in, W1, W2, W_out);              // 1
    k_hist<<<(N_EDGES + 255) / 256, 256>>>(dst);                      // 2
    k_scan_fused<<<1, 1024>>>();                                      // 3
    k_gemm_mma<true, false, false><<<gNarrow, 256, SMEM_GEMM>>>(      // 4 (profiled)
        xhi, xlo, winh, winl, b_in, nullptr, h, nullptr, nullptr,
        N_NODES, D_IN, D_H);
    k_fill<<<(N_EDGES + 255) / 256, 256>>>(src, dst, self_w, ppi_w);  // 5

    k_aggregate<<<aggBlocks, 256>>>();                                // 6
    k_gemm_mma<true, true, false><<<gNarrow, 256, SMEM_GEMM>>>(       // 7
        ahi, alo, w1h, w1l, b1, res, h, nullptr, nullptr,
        N_NODES, D_H, D_H);
    k_aggregate<<<aggBlocks, 256>>>();                                // 8
    k_gemm_mma<true, true, true><<<gNarrow, 256, SMEM_GEMM>>>(        // 9
        ahi, alo, w2h, w2l, b2, res, nullptr, hhi, hlo,
        N_NODES, D_H, D_H);

    k_gemm_mma<false, false, false><<<gOut, 256, SMEM_GEMM>>>(        // 10
        hhi, hlo, woh, wol, b_out, nullptr, out, nullptr, nullptr,
        N_NODES, D_H, N_LABELS);
}